// round 7
// baseline (speedup 1.0000x reference)
#include <cuda_runtime.h>
#include <cuda_bf16.h>
#include <cstdint>

// Problem constants (fixed by setup_inputs)
#define BATCH 4
#define IMG 256
#define WS 8
#define NW 1024              // (256/8)^2
#define BWIN (BATCH * NW)    // 4096 windows
#define NTOK 64              // WS*WS
#define CH 256
#define HEADS 8
#define HD 32
#define MTOT (BWIN * NTOK)   // 262144 rows

// Scratch
__device__ float g_Q[(size_t)MTOT * CH];
__device__ float g_K[(size_t)MTOT * CH];
__device__ float g_V[(size_t)MTOT * CH];
__device__ float g_S[(size_t)MTOT * CH];

// ---------------------------------------------------------------------------
// helpers (sm_80-generic; compute_103-safe)
// ---------------------------------------------------------------------------
__device__ __forceinline__ uint32_t tf32_rna(float x) {
    uint32_t y;
    asm("cvt.rna.tf32.f32 %0, %1;" : "=r"(y) : "f"(x));
    return y;
}
__device__ __forceinline__ void mma_tf32(float* d, const uint32_t* a, const uint32_t* b) {
    asm volatile(
        "mma.sync.aligned.m16n8k8.row.col.f32.tf32.tf32.f32 "
        "{%0,%1,%2,%3}, {%4,%5,%6,%7}, {%8,%9}, {%0,%1,%2,%3};"
        : "+f"(d[0]), "+f"(d[1]), "+f"(d[2]), "+f"(d[3])
        : "r"(a[0]), "r"(a[1]), "r"(a[2]), "r"(a[3]), "r"(b[0]), "r"(b[1]));
}
__device__ __forceinline__ uint32_t smem_u32(const void* p) {
    uint32_t a;
    asm("{ .reg .u64 t; cvta.to.shared.u64 t, %1; cvt.u32.u64 %0, t; }" : "=r"(a) : "l"(p));
    return a;
}
__device__ __forceinline__ void cp16(void* dst, const void* src) {
    uint32_t d = smem_u32(dst);
    asm volatile("cp.async.cg.shared.global [%0], [%1], 16;" :: "r"(d), "l"(src));
}
#define CP_COMMIT() asm volatile("cp.async.commit_group;" ::: "memory")
#define CP_WAIT1()  asm volatile("cp.async.wait_group 1;" ::: "memory")

// ---------------------------------------------------------------------------
// GEMM via mma.sync tf32, 3-stage cp.async pipeline (single barrier per kc):
// C[M x 256] = A[M x 256] @ Wt^T + bias
// Block 256 thr (8 warps, 2x4), tile 128x128x32, warp tile 64x32.
// ---------------------------------------------------------------------------
#define GP 36                                   // fp32 row stride in smem (pad)
#define GEMM_SMEM (3 * 2 * 128 * GP * 4)        // 110592 B

__global__ __launch_bounds__(256) void gemm_mma(
    const float* __restrict__ A, const float* __restrict__ Wt,
    const float* __restrict__ bias, float* __restrict__ C)
{
    extern __shared__ float gsm[];
    float* As = gsm;                 // [3][128][GP]
    float* Bs = gsm + 3 * 128 * GP;  // [3][128][GP]

    const int t = threadIdx.x, lane = t & 31, warp = t >> 5;
    const int wm = warp & 1, wn = warp >> 1;         // 2 x 4 warp grid
    const int m0 = blockIdx.y * 128, n0 = blockIdx.x * 128;
    const int g = lane >> 2, tg = lane & 3;

    const int lrow = t >> 3;            // 0..31 (+32*i)
    const int lc4  = (t & 7) * 4;       // 0..28

    float acc[4][4][4];
#pragma unroll
    for (int mi = 0; mi < 4; mi++)
#pragma unroll
        for (int ni = 0; ni < 4; ni++)
#pragma unroll
            for (int r = 0; r < 4; r++) acc[mi][ni][r] = 0.f;

    // prologue: tiles 0,1 -> bufs 0,1
#pragma unroll
    for (int s = 0; s < 2; s++) {
#pragma unroll
        for (int i = 0; i < 4; i++) {
            int row = lrow + i * 32;
            cp16(&As[(s * 128 + row) * GP + lc4], A  + (size_t)(m0 + row) * 256 + s * 32 + lc4);
            cp16(&Bs[(s * 128 + row) * GP + lc4], Wt + (size_t)(n0 + row) * 256 + s * 32 + lc4);
        }
        CP_COMMIT();
    }

    for (int kc = 0; kc < 8; kc++) {
        CP_WAIT1();            // tile kc resident
        __syncthreads();       // also: all warps done with buf (kc+2)%3 (= kc-1's compute)

        if (kc < 6) {
            int buf = (kc + 2) % 3;
            int ko = (kc + 2) * 32;
#pragma unroll
            for (int i = 0; i < 4; i++) {
                int row = lrow + i * 32;
                cp16(&As[(buf * 128 + row) * GP + lc4], A  + (size_t)(m0 + row) * 256 + ko + lc4);
                cp16(&Bs[(buf * 128 + row) * GP + lc4], Wt + (size_t)(n0 + row) * 256 + ko + lc4);
            }
        }
        CP_COMMIT();

        const float* Ab = As + (kc % 3) * 128 * GP;
        const float* Bb = Bs + (kc % 3) * 128 * GP;
#pragma unroll
        for (int ks = 0; ks < 4; ks++) {
            const int k0 = ks * 8;
            uint32_t a[4][4], b[4][2];
#pragma unroll
            for (int mi = 0; mi < 4; mi++) {
                int r = wm * 64 + mi * 16 + g;
                a[mi][0] = tf32_rna(Ab[r * GP + k0 + tg]);
                a[mi][1] = tf32_rna(Ab[(r + 8) * GP + k0 + tg]);
                a[mi][2] = tf32_rna(Ab[r * GP + k0 + tg + 4]);
                a[mi][3] = tf32_rna(Ab[(r + 8) * GP + k0 + tg + 4]);
            }
#pragma unroll
            for (int ni = 0; ni < 4; ni++) {
                int r = wn * 32 + ni * 8 + g;
                b[ni][0] = tf32_rna(Bb[r * GP + k0 + tg]);
                b[ni][1] = tf32_rna(Bb[r * GP + k0 + tg + 4]);
            }
#pragma unroll
            for (int mi = 0; mi < 4; mi++)
#pragma unroll
                for (int ni = 0; ni < 4; ni++)
                    mma_tf32(acc[mi][ni], a[mi], b[ni]);
        }
    }

    float bv[4][2];
#pragma unroll
    for (int ni = 0; ni < 4; ni++) {
        int col = n0 + wn * 32 + ni * 8 + 2 * tg;
        bv[ni][0] = __ldg(bias + col);
        bv[ni][1] = __ldg(bias + col + 1);
    }
#pragma unroll
    for (int mi = 0; mi < 4; mi++) {
        int r0 = m0 + wm * 64 + mi * 16 + g;
#pragma unroll
        for (int ni = 0; ni < 4; ni++) {
            int col = n0 + wn * 32 + ni * 8 + 2 * tg;
            *(float2*)(C + (size_t)r0 * 256 + col) =
                make_float2(acc[mi][ni][0] + bv[ni][0], acc[mi][ni][1] + bv[ni][1]);
            *(float2*)(C + (size_t)(r0 + 8) * 256 + col) =
                make_float2(acc[mi][ni][2] + bv[ni][0], acc[mi][ni][3] + bv[ni][1]);
        }
    }
}

// ---------------------------------------------------------------------------
// Attention v3. Block = 128 thr (4 warps) per (window, head-pair).
// Q fragments loaded straight from global (warp-exclusive slice).
// smem: P region [4 warps][32][36] (4608 w, aliases Ks [64][68] = 4352 w),
//       Vs [64][68] at offset 4608.  Total 35840 B -> 5 CTAs/SM.
// Softmax normalizes acc in place; PV done in two k-halves via per-warp P buf.
// ---------------------------------------------------------------------------
#define AT 68
#define PT 36
#define ATTN_SMEM ((4 * 32 * PT + 64 * AT) * 4)   // (4608 + 4352)*4 = 35840 B

__global__ __launch_bounds__(128, 5) void attn_mma(
    const float* __restrict__ Q, const float* __restrict__ K,
    const float* __restrict__ V, const float* __restrict__ mask,
    float* __restrict__ S)
{
    extern __shared__ uint32_t sm[];
    uint32_t* Ks = sm;                       // [64][AT] (aliased by P later)
    uint32_t* Vs = sm + 4 * 32 * PT;         // [64][AT]

    const int hp = blockIdx.x;      // 0..3 head-pair
    const int b  = blockIdx.y;      // 0..4095
    const int t = threadIdx.x, lane = t & 31, w = t >> 5;
    const int g = lane >> 2, tg = lane & 3;
    const size_t base = (size_t)b * NTOK * CH + hp * 64;
    const float scale = 0.17677669529663687f; // 32^-0.5

    // stage K, V channel slice as tf32
#pragma unroll
    for (int i = 0; i < 8; i++) {
        int idx = i * 128 + t;
        int row = idx >> 4;            // 0..63
        int cq  = (idx & 15) * 4;      // 0..60
        const float4 k4 = *(const float4*)(K + base + (size_t)row * 256 + cq);
        const float4 v4 = *(const float4*)(V + base + (size_t)row * 256 + cq);
        uint32_t* kp = Ks + row * AT + cq;
        kp[0] = tf32_rna(k4.x); kp[1] = tf32_rna(k4.y);
        kp[2] = tf32_rna(k4.z); kp[3] = tf32_rna(k4.w);
        uint32_t* vp = Vs + row * AT + cq;
        vp[0] = tf32_rna(v4.x); vp[1] = tf32_rna(v4.y);
        vp[2] = tf32_rna(v4.z); vp[3] = tf32_rna(v4.w);
    }
    __syncthreads();

    const int ch0 = (w >> 1) * 32;    // head channel offset within slice
    const int rbase = (w & 1) * 32;   // token-row base

    // Q row pointers (warp-exclusive slice of Q)
    const float* Qr[2][2];
#pragma unroll
    for (int mi = 0; mi < 2; mi++) {
        int r = rbase + mi * 16 + g;
        Qr[mi][0] = Q + base + (size_t)r * 256 + ch0;
        Qr[mi][1] = Q + base + (size_t)(r + 8) * 256 + ch0;
    }

    // scores: acc[mi][ni][4], rows rbase+mi*16+{g,g+8}, cols ni*8+2tg+{0,1}
    float acc[2][8][4];
#pragma unroll
    for (int mi = 0; mi < 2; mi++)
#pragma unroll
        for (int ni = 0; ni < 8; ni++)
#pragma unroll
            for (int r = 0; r < 4; r++) acc[mi][ni][r] = 0.f;

#pragma unroll
    for (int ks = 0; ks < 4; ks++) {
        const int kq = ks * 8;           // channel offset within head
        uint32_t a[2][4], bb[8][2];
#pragma unroll
        for (int mi = 0; mi < 2; mi++) {
            a[mi][0] = tf32_rna(Qr[mi][0][kq + tg] * scale);
            a[mi][1] = tf32_rna(Qr[mi][1][kq + tg] * scale);
            a[mi][2] = tf32_rna(Qr[mi][0][kq + tg + 4] * scale);
            a[mi][3] = tf32_rna(Qr[mi][1][kq + tg + 4] * scale);
        }
        const int k0 = ch0 + kq;
#pragma unroll
        for (int ni = 0; ni < 8; ni++) {
            int r = ni * 8 + g;
            bb[ni][0] = Ks[r * AT + k0 + tg];
            bb[ni][1] = Ks[r * AT + k0 + tg + 4];
        }
#pragma unroll
        for (int mi = 0; mi < 2; mi++)
#pragma unroll
            for (int ni = 0; ni < 8; ni++)
                mma_tf32(acc[mi][ni], a[mi], bb[ni]);
    }

    // mask + softmax: normalize acc IN PLACE (P stays in registers)
    const float* mp = mask + (size_t)(b & (NW - 1)) * NTOK * NTOK;
#pragma unroll
    for (int mi = 0; mi < 2; mi++) {
#pragma unroll
        for (int rh = 0; rh < 2; rh++) {
            const int row = rbase + mi * 16 + rh * 8 + g;
            const int o = rh * 2;
            float mx = -1e30f;
#pragma unroll
            for (int ni = 0; ni < 8; ni++) {
                float2 mv = *(const float2*)(mp + row * 64 + ni * 8 + 2 * tg);
                acc[mi][ni][o]     += mv.x;
                acc[mi][ni][o + 1] += mv.y;
                mx = fmaxf(mx, fmaxf(acc[mi][ni][o], acc[mi][ni][o + 1]));
            }
            mx = fmaxf(mx, __shfl_xor_sync(0xffffffffu, mx, 1));
            mx = fmaxf(mx, __shfl_xor_sync(0xffffffffu, mx, 2));
            float sum = 0.f;
#pragma unroll
            for (int ni = 0; ni < 8; ni++) {
                acc[mi][ni][o]     = __expf(acc[mi][ni][o] - mx);
                acc[mi][ni][o + 1] = __expf(acc[mi][ni][o + 1] - mx);
                sum += acc[mi][ni][o] + acc[mi][ni][o + 1];
            }
            sum += __shfl_xor_sync(0xffffffffu, sum, 1);
            sum += __shfl_xor_sync(0xffffffffu, sum, 2);
            const float inv = 1.f / sum;
#pragma unroll
            for (int ni = 0; ni < 8; ni++) {
                acc[mi][ni][o]     *= inv;
                acc[mi][ni][o + 1] *= inv;
            }
        }
    }

    // all warps done reading Ks -> its smem becomes the P region
    __syncthreads();

    // O = P @ V in two k-halves through per-warp P buffer [32][PT]
    float acc2[2][4][4];
#pragma unroll
    for (int mi = 0; mi < 2; mi++)
#pragma unroll
        for (int ni = 0; ni < 4; ni++)
#pragma unroll
            for (int r = 0; r < 4; r++) acc2[mi][ni][r] = 0.f;

    uint32_t* Pw = sm + w * 32 * PT;
#pragma unroll
    for (int h = 0; h < 2; h++) {
        // store this k-half of P (cols 32h..32h+31) as tf32
#pragma unroll
        for (int mi = 0; mi < 2; mi++)
#pragma unroll
            for (int rh = 0; rh < 2; rh++) {
                const int rl = mi * 16 + rh * 8 + g;
#pragma unroll
                for (int ni = 0; ni < 4; ni++) {
                    uint2 pv;
                    pv.x = tf32_rna(acc[mi][4 * h + ni][rh * 2]);
                    pv.y = tf32_rna(acc[mi][4 * h + ni][rh * 2 + 1]);
                    *(uint2*)(Pw + rl * PT + ni * 8 + 2 * tg) = pv;
                }
            }
        __syncwarp();
#pragma unroll
        for (int ks = 0; ks < 4; ks++) {
            const int kg = 32 * h + ks * 8;     // global k (token index)
            uint32_t a[2][4], bb[4][2];
#pragma unroll
            for (int mi = 0; mi < 2; mi++) {
                int rl = mi * 16 + g;
                a[mi][0] = Pw[rl * PT + ks * 8 + tg];
                a[mi][1] = Pw[(rl + 8) * PT + ks * 8 + tg];
                a[mi][2] = Pw[rl * PT + ks * 8 + tg + 4];
                a[mi][3] = Pw[(rl + 8) * PT + ks * 8 + tg + 4];
            }
#pragma unroll
            for (int ni = 0; ni < 4; ni++) {
                bb[ni][0] = Vs[(kg + tg) * AT + ch0 + ni * 8 + g];
                bb[ni][1] = Vs[(kg + tg + 4) * AT + ch0 + ni * 8 + g];
            }
#pragma unroll
            for (int mi = 0; mi < 2; mi++)
#pragma unroll
                for (int ni = 0; ni < 4; ni++)
                    mma_tf32(acc2[mi][ni], a[mi], bb[ni]);
        }
        __syncwarp();
    }

#pragma unroll
    for (int mi = 0; mi < 2; mi++) {
        const int row = rbase + mi * 16 + g;
#pragma unroll
        for (int ni = 0; ni < 4; ni++) {
            const int col = hp * 64 + ch0 + ni * 8 + 2 * tg;
            *(float2*)(S + (size_t)(b * NTOK + row) * 256 + col) =
                make_float2(acc2[mi][ni][0], acc2[mi][ni][1]);
            *(float2*)(S + (size_t)(b * NTOK + row + 8) * 256 + col) =
                make_float2(acc2[mi][ni][2], acc2[mi][ni][3]);
        }
    }
}

// ---------------------------------------------------------------------------
// LePE depthwise 3x3 conv, accumulated into g_S. (unchanged)
// ---------------------------------------------------------------------------
__global__ __launch_bounds__(256) void lepe_kernel(
    const float* __restrict__ Q, const float* __restrict__ rw,
    const float* __restrict__ rb, float* __restrict__ S)
{
    __shared__ float sm[100][64];

    const int win = blockIdx.x;
    const int b = blockIdx.y;
    const int cb = blockIdx.z * 64;
    const int wr = win >> 5, wc = win & 31;
    const int hh0 = wr * 8, ww0 = wc * 8;
    const int t = threadIdx.x;
    const int c = t & 63, p0 = t >> 6;

    for (int p = p0; p < 100; p += 4) {
        int py = p / 10, px = p % 10;
        int hh = hh0 + py - 1, ww = ww0 + px - 1;
        float v = 0.f;
        if (hh >= 0 && hh < IMG && ww >= 0 && ww < IMG) {
            size_t idx = (((size_t)(b * NW + (hh >> 3) * 32 + (ww >> 3))) * NTOK
                          + ((hh & 7) * 8 + (ww & 7))) * (size_t)CH + cb + c;
            v = Q[idx];
        }
        sm[p][c] = v;
    }
    __syncthreads();

    float w[9];
#pragma unroll
    for (int k = 0; k < 9; k++) w[k] = rw[(cb + c) * 9 + k];
    const float bias = rb[cb + c];

    const size_t sbase = (((size_t)(b * NW + win)) * NTOK) * CH + cb + c;
    for (int p = p0; p < 64; p += 4) {
        int py = p >> 3, px = p & 7;
        float acc = bias;
#pragma unroll
        for (int dy = 0; dy < 3; dy++)
#pragma unroll
            for (int dx = 0; dx < 3; dx++)
                acc = fmaf(sm[(py + dy) * 10 + (px + dx)][c], w[dy * 3 + dx], acc);
        S[sbase + (size_t)p * CH] += acc;
    }
}

// ---------------------------------------------------------------------------
// kernel_launch
// ---------------------------------------------------------------------------
extern "C" void kernel_launch(void* const* d_in, const int* in_sizes, int n_in,
                              void* d_out, int out_size)
{
    const float* x    = (const float*)d_in[0];
    const float* y    = (const float*)d_in[1];
    const float* mask = (const float*)d_in[2];
    const float* Wq   = (const float*)d_in[3];
    const float* bq   = (const float*)d_in[4];
    const float* Wk   = (const float*)d_in[5];
    const float* bk   = (const float*)d_in[6];
    const float* Wv   = (const float*)d_in[7];
    const float* bv   = (const float*)d_in[8];
    const float* rw   = (const float*)d_in[9];
    const float* rb   = (const float*)d_in[10];
    const float* Wp   = (const float*)d_in[11];
    const float* bp   = (const float*)d_in[12];
    float* out        = (float*)d_out;

    float *pQ, *pK, *pV, *pS;
    cudaGetSymbolAddress((void**)&pQ, g_Q);
    cudaGetSymbolAddress((void**)&pK, g_K);
    cudaGetSymbolAddress((void**)&pV, g_V);
    cudaGetSymbolAddress((void**)&pS, g_S);

    static bool attr_done = false;
    if (!attr_done) {
        cudaFuncSetAttribute(gemm_mma, cudaFuncAttributeMaxDynamicSharedMemorySize, GEMM_SMEM);
        cudaFuncSetAttribute(attn_mma, cudaFuncAttributeMaxDynamicSharedMemorySize, ATTN_SMEM);
        attr_done = true;
    }

    dim3 gg(2, MTOT / 128);   // (256/128, 262144/128)
    gemm_mma<<<gg, 256, GEMM_SMEM>>>(x, Wq, bq, pQ);
    gemm_mma<<<gg, 256, GEMM_SMEM>>>(y, Wk, bk, pK);
    gemm_mma<<<gg, 256, GEMM_SMEM>>>(x, Wv, bv, pV);

    attn_mma<<<dim3(4, BWIN), 128, ATTN_SMEM>>>(pQ, pK, pV, mask, pS);

    lepe_kernel<<<dim3(NW, BATCH, 4), 256>>>(pQ, rw, rb, pS);

    gemm_mma<<<gg, 256, GEMM_SMEM>>>(pS, Wp, bp, out);
}

// round 8
// speedup vs baseline: 1.0296x; 1.0296x over previous
#include <cuda_runtime.h>
#include <cuda_bf16.h>
#include <cstdint>

// Problem constants (fixed by setup_inputs)
#define BATCH 4
#define IMG 256
#define WS 8
#define NW 1024              // (256/8)^2
#define BWIN (BATCH * NW)    // 4096 windows
#define NTOK 64              // WS*WS
#define CH 256
#define HEADS 8
#define HD 32
#define MTOT (BWIN * NTOK)   // 262144 rows

// Scratch
__device__ float g_Q[(size_t)MTOT * CH];
__device__ float g_K[(size_t)MTOT * CH];
__device__ float g_V[(size_t)MTOT * CH];
__device__ float g_S[(size_t)MTOT * CH];

// ---------------------------------------------------------------------------
// helpers (sm_80-generic; compute_103-safe)
// ---------------------------------------------------------------------------
__device__ __forceinline__ uint32_t tf32_rna(float x) {
    uint32_t y;
    asm("cvt.rna.tf32.f32 %0, %1;" : "=r"(y) : "f"(x));
    return y;
}
__device__ __forceinline__ void mma_tf32(float* d, const uint32_t* a, const uint32_t* b) {
    asm volatile(
        "mma.sync.aligned.m16n8k8.row.col.f32.tf32.tf32.f32 "
        "{%0,%1,%2,%3}, {%4,%5,%6,%7}, {%8,%9}, {%0,%1,%2,%3};"
        : "+f"(d[0]), "+f"(d[1]), "+f"(d[2]), "+f"(d[3])
        : "r"(a[0]), "r"(a[1]), "r"(a[2]), "r"(a[3]), "r"(b[0]), "r"(b[1]));
}
__device__ __forceinline__ uint32_t smem_u32(const void* p) {
    uint32_t a;
    asm("{ .reg .u64 t; cvta.to.shared.u64 t, %1; cvt.u32.u64 %0, t; }" : "=r"(a) : "l"(p));
    return a;
}
__device__ __forceinline__ void cp16(void* dst, const void* src) {
    uint32_t d = smem_u32(dst);
    asm volatile("cp.async.cg.shared.global [%0], [%1], 16;" :: "r"(d), "l"(src));
}
#define CP_COMMIT() asm volatile("cp.async.commit_group;" ::: "memory")
#define CP_WAIT0()  asm volatile("cp.async.wait_group 0;" ::: "memory")

// ---------------------------------------------------------------------------
// GEMM via mma.sync tf32, 2-stage double buffer, ONE barrier per k-chunk:
// C[M x 256] = A[M x 256] @ Wt^T + bias
// Block 256 thr (8 warps, 2x4), tile 128x128x32, warp tile 64x32.
// 73.7 KB smem -> 3-CTA-eligible; prefetch overlaps compute via cp.async.
// ---------------------------------------------------------------------------
#define GP 36                                   // fp32 row stride in smem (pad)
#define GEMM_SMEM (2 * 2 * 128 * GP * 4)        // 73728 B

__global__ __launch_bounds__(256) void gemm_mma(
    const float* __restrict__ A, const float* __restrict__ Wt,
    const float* __restrict__ bias, float* __restrict__ C)
{
    extern __shared__ float gsm[];
    float* As = gsm;                 // [2][128][GP]
    float* Bs = gsm + 2 * 128 * GP;  // [2][128][GP]

    const int t = threadIdx.x, lane = t & 31, warp = t >> 5;
    const int wm = warp & 1, wn = warp >> 1;         // 2 x 4 warp grid
    const int m0 = blockIdx.y * 128, n0 = blockIdx.x * 128;
    const int g = lane >> 2, tg = lane & 3;

    const int lrow = t >> 3;            // 0..31 (+32*i)
    const int lc4  = (t & 7) * 4;       // 0..28

    float acc[4][4][4];
#pragma unroll
    for (int mi = 0; mi < 4; mi++)
#pragma unroll
        for (int ni = 0; ni < 4; ni++)
#pragma unroll
            for (int r = 0; r < 4; r++) acc[mi][ni][r] = 0.f;

    // prologue: tile 0 -> buf 0
#pragma unroll
    for (int i = 0; i < 4; i++) {
        int row = lrow + i * 32;
        cp16(&As[row * GP + lc4], A  + (size_t)(m0 + row) * 256 + lc4);
        cp16(&Bs[row * GP + lc4], Wt + (size_t)(n0 + row) * 256 + lc4);
    }
    CP_COMMIT();

    for (int kc = 0; kc < 8; kc++) {
        CP_WAIT0();            // tile kc resident
        __syncthreads();       // all warps past compute(kc-1) -> buf^1 reusable

        if (kc < 7) {
            int buf = (kc + 1) & 1;
            int ko = (kc + 1) * 32;
#pragma unroll
            for (int i = 0; i < 4; i++) {
                int row = lrow + i * 32;
                cp16(&As[(buf * 128 + row) * GP + lc4], A  + (size_t)(m0 + row) * 256 + ko + lc4);
                cp16(&Bs[(buf * 128 + row) * GP + lc4], Wt + (size_t)(n0 + row) * 256 + ko + lc4);
            }
            CP_COMMIT();
        }

        const float* Ab = As + (kc & 1) * 128 * GP;
        const float* Bb = Bs + (kc & 1) * 128 * GP;
#pragma unroll
        for (int ks = 0; ks < 4; ks++) {
            const int k0 = ks * 8;
            uint32_t a[4][4], b[4][2];
#pragma unroll
            for (int mi = 0; mi < 4; mi++) {
                int r = wm * 64 + mi * 16 + g;
                a[mi][0] = tf32_rna(Ab[r * GP + k0 + tg]);
                a[mi][1] = tf32_rna(Ab[(r + 8) * GP + k0 + tg]);
                a[mi][2] = tf32_rna(Ab[r * GP + k0 + tg + 4]);
                a[mi][3] = tf32_rna(Ab[(r + 8) * GP + k0 + tg + 4]);
            }
#pragma unroll
            for (int ni = 0; ni < 4; ni++) {
                int r = wn * 32 + ni * 8 + g;
                b[ni][0] = tf32_rna(Bb[r * GP + k0 + tg]);
                b[ni][1] = tf32_rna(Bb[r * GP + k0 + tg + 4]);
            }
#pragma unroll
            for (int mi = 0; mi < 4; mi++)
#pragma unroll
                for (int ni = 0; ni < 4; ni++)
                    mma_tf32(acc[mi][ni], a[mi], b[ni]);
        }
    }

    float bv[4][2];
#pragma unroll
    for (int ni = 0; ni < 4; ni++) {
        int col = n0 + wn * 32 + ni * 8 + 2 * tg;
        bv[ni][0] = __ldg(bias + col);
        bv[ni][1] = __ldg(bias + col + 1);
    }
#pragma unroll
    for (int mi = 0; mi < 4; mi++) {
        int r0 = m0 + wm * 64 + mi * 16 + g;
#pragma unroll
        for (int ni = 0; ni < 4; ni++) {
            int col = n0 + wn * 32 + ni * 8 + 2 * tg;
            *(float2*)(C + (size_t)r0 * 256 + col) =
                make_float2(acc[mi][ni][0] + bv[ni][0], acc[mi][ni][1] + bv[ni][1]);
            *(float2*)(C + (size_t)(r0 + 8) * 256 + col) =
                make_float2(acc[mi][ni][2] + bv[ni][0], acc[mi][ni][3] + bv[ni][1]);
        }
    }
}

// ---------------------------------------------------------------------------
// Attention v3. Block = 128 thr (4 warps) per (window, head-pair).
// Q fragments loaded straight from global (warp-exclusive slice).
// smem: P region [4 warps][32][36] (4608 w, aliases Ks [64][68] = 4352 w),
//       Vs [64][68] at offset 4608.  Total 35840 B -> 5 CTAs/SM.
// Softmax normalizes acc in place; PV done in two k-halves via per-warp P buf.
// ---------------------------------------------------------------------------
#define AT 68
#define PT 36
#define ATTN_SMEM ((4 * 32 * PT + 64 * AT) * 4)   // (4608 + 4352)*4 = 35840 B

__global__ __launch_bounds__(128, 5) void attn_mma(
    const float* __restrict__ Q, const float* __restrict__ K,
    const float* __restrict__ V, const float* __restrict__ mask,
    float* __restrict__ S)
{
    extern __shared__ uint32_t sm[];
    uint32_t* Ks = sm;                       // [64][AT] (aliased by P later)
    uint32_t* Vs = sm + 4 * 32 * PT;         // [64][AT]

    const int hp = blockIdx.x;      // 0..3 head-pair
    const int b  = blockIdx.y;      // 0..4095
    const int t = threadIdx.x, lane = t & 31, w = t >> 5;
    const int g = lane >> 2, tg = lane & 3;
    const size_t base = (size_t)b * NTOK * CH + hp * 64;
    const float scale = 0.17677669529663687f; // 32^-0.5

    // stage K, V channel slice as tf32
#pragma unroll
    for (int i = 0; i < 8; i++) {
        int idx = i * 128 + t;
        int row = idx >> 4;            // 0..63
        int cq  = (idx & 15) * 4;      // 0..60
        const float4 k4 = *(const float4*)(K + base + (size_t)row * 256 + cq);
        const float4 v4 = *(const float4*)(V + base + (size_t)row * 256 + cq);
        uint32_t* kp = Ks + row * AT + cq;
        kp[0] = tf32_rna(k4.x); kp[1] = tf32_rna(k4.y);
        kp[2] = tf32_rna(k4.z); kp[3] = tf32_rna(k4.w);
        uint32_t* vp = Vs + row * AT + cq;
        vp[0] = tf32_rna(v4.x); vp[1] = tf32_rna(v4.y);
        vp[2] = tf32_rna(v4.z); vp[3] = tf32_rna(v4.w);
    }
    __syncthreads();

    const int ch0 = (w >> 1) * 32;    // head channel offset within slice
    const int rbase = (w & 1) * 32;   // token-row base

    // Q row pointers (warp-exclusive slice of Q)
    const float* Qr[2][2];
#pragma unroll
    for (int mi = 0; mi < 2; mi++) {
        int r = rbase + mi * 16 + g;
        Qr[mi][0] = Q + base + (size_t)r * 256 + ch0;
        Qr[mi][1] = Q + base + (size_t)(r + 8) * 256 + ch0;
    }

    // scores: acc[mi][ni][4], rows rbase+mi*16+{g,g+8}, cols ni*8+2tg+{0,1}
    float acc[2][8][4];
#pragma unroll
    for (int mi = 0; mi < 2; mi++)
#pragma unroll
        for (int ni = 0; ni < 8; ni++)
#pragma unroll
            for (int r = 0; r < 4; r++) acc[mi][ni][r] = 0.f;

#pragma unroll
    for (int ks = 0; ks < 4; ks++) {
        const int kq = ks * 8;           // channel offset within head
        uint32_t a[2][4], bb[8][2];
#pragma unroll
        for (int mi = 0; mi < 2; mi++) {
            a[mi][0] = tf32_rna(Qr[mi][0][kq + tg] * scale);
            a[mi][1] = tf32_rna(Qr[mi][1][kq + tg] * scale);
            a[mi][2] = tf32_rna(Qr[mi][0][kq + tg + 4] * scale);
            a[mi][3] = tf32_rna(Qr[mi][1][kq + tg + 4] * scale);
        }
        const int k0 = ch0 + kq;
#pragma unroll
        for (int ni = 0; ni < 8; ni++) {
            int r = ni * 8 + g;
            bb[ni][0] = Ks[r * AT + k0 + tg];
            bb[ni][1] = Ks[r * AT + k0 + tg + 4];
        }
#pragma unroll
        for (int mi = 0; mi < 2; mi++)
#pragma unroll
            for (int ni = 0; ni < 8; ni++)
                mma_tf32(acc[mi][ni], a[mi], bb[ni]);
    }

    // mask + softmax: normalize acc IN PLACE (P stays in registers)
    const float* mp = mask + (size_t)(b & (NW - 1)) * NTOK * NTOK;
#pragma unroll
    for (int mi = 0; mi < 2; mi++) {
#pragma unroll
        for (int rh = 0; rh < 2; rh++) {
            const int row = rbase + mi * 16 + rh * 8 + g;
            const int o = rh * 2;
            float mx = -1e30f;
#pragma unroll
            for (int ni = 0; ni < 8; ni++) {
                float2 mv = *(const float2*)(mp + row * 64 + ni * 8 + 2 * tg);
                acc[mi][ni][o]     += mv.x;
                acc[mi][ni][o + 1] += mv.y;
                mx = fmaxf(mx, fmaxf(acc[mi][ni][o], acc[mi][ni][o + 1]));
            }
            mx = fmaxf(mx, __shfl_xor_sync(0xffffffffu, mx, 1));
            mx = fmaxf(mx, __shfl_xor_sync(0xffffffffu, mx, 2));
            float sum = 0.f;
#pragma unroll
            for (int ni = 0; ni < 8; ni++) {
                acc[mi][ni][o]     = __expf(acc[mi][ni][o] - mx);
                acc[mi][ni][o + 1] = __expf(acc[mi][ni][o + 1] - mx);
                sum += acc[mi][ni][o] + acc[mi][ni][o + 1];
            }
            sum += __shfl_xor_sync(0xffffffffu, sum, 1);
            sum += __shfl_xor_sync(0xffffffffu, sum, 2);
            const float inv = 1.f / sum;
#pragma unroll
            for (int ni = 0; ni < 8; ni++) {
                acc[mi][ni][o]     *= inv;
                acc[mi][ni][o + 1] *= inv;
            }
        }
    }

    // all warps done reading Ks -> its smem becomes the P region
    __syncthreads();

    // O = P @ V in two k-halves through per-warp P buffer [32][PT]
    float acc2[2][4][4];
#pragma unroll
    for (int mi = 0; mi < 2; mi++)
#pragma unroll
        for (int ni = 0; ni < 4; ni++)
#pragma unroll
            for (int r = 0; r < 4; r++) acc2[mi][ni][r] = 0.f;

    uint32_t* Pw = sm + w * 32 * PT;
#pragma unroll
    for (int h = 0; h < 2; h++) {
        // store this k-half of P (cols 32h..32h+31) as tf32
#pragma unroll
        for (int mi = 0; mi < 2; mi++)
#pragma unroll
            for (int rh = 0; rh < 2; rh++) {
                const int rl = mi * 16 + rh * 8 + g;
#pragma unroll
                for (int ni = 0; ni < 4; ni++) {
                    uint2 pv;
                    pv.x = tf32_rna(acc[mi][4 * h + ni][rh * 2]);
                    pv.y = tf32_rna(acc[mi][4 * h + ni][rh * 2 + 1]);
                    *(uint2*)(Pw + rl * PT + ni * 8 + 2 * tg) = pv;
                }
            }
        __syncwarp();
#pragma unroll
        for (int ks = 0; ks < 4; ks++) {
            const int kg = 32 * h + ks * 8;     // global k (token index)
            uint32_t a[2][4], bb[4][2];
#pragma unroll
            for (int mi = 0; mi < 2; mi++) {
                int rl = mi * 16 + g;
                a[mi][0] = Pw[rl * PT + ks * 8 + tg];
                a[mi][1] = Pw[(rl + 8) * PT + ks * 8 + tg];
                a[mi][2] = Pw[rl * PT + ks * 8 + tg + 4];
                a[mi][3] = Pw[(rl + 8) * PT + ks * 8 + tg + 4];
            }
#pragma unroll
            for (int ni = 0; ni < 4; ni++) {
                bb[ni][0] = Vs[(kg + tg) * AT + ch0 + ni * 8 + g];
                bb[ni][1] = Vs[(kg + tg + 4) * AT + ch0 + ni * 8 + g];
            }
#pragma unroll
            for (int mi = 0; mi < 2; mi++)
#pragma unroll
                for (int ni = 0; ni < 4; ni++)
                    mma_tf32(acc2[mi][ni], a[mi], bb[ni]);
        }
        __syncwarp();
    }

#pragma unroll
    for (int mi = 0; mi < 2; mi++) {
        const int row = rbase + mi * 16 + g;
#pragma unroll
        for (int ni = 0; ni < 4; ni++) {
            const int col = hp * 64 + ch0 + ni * 8 + 2 * tg;
            *(float2*)(S + (size_t)(b * NTOK + row) * 256 + col) =
                make_float2(acc2[mi][ni][0], acc2[mi][ni][1]);
            *(float2*)(S + (size_t)(b * NTOK + row + 8) * 256 + col) =
                make_float2(acc2[mi][ni][2], acc2[mi][ni][3]);
        }
    }
}

// ---------------------------------------------------------------------------
// LePE depthwise 3x3 conv, accumulated into g_S. (unchanged)
// ---------------------------------------------------------------------------
__global__ __launch_bounds__(256) void lepe_kernel(
    const float* __restrict__ Q, const float* __restrict__ rw,
    const float* __restrict__ rb, float* __restrict__ S)
{
    __shared__ float sm[100][64];

    const int win = blockIdx.x;
    const int b = blockIdx.y;
    const int cb = blockIdx.z * 64;
    const int wr = win >> 5, wc = win & 31;
    const int hh0 = wr * 8, ww0 = wc * 8;
    const int t = threadIdx.x;
    const int c = t & 63, p0 = t >> 6;

    for (int p = p0; p < 100; p += 4) {
        int py = p / 10, px = p % 10;
        int hh = hh0 + py - 1, ww = ww0 + px - 1;
        float v = 0.f;
        if (hh >= 0 && hh < IMG && ww >= 0 && ww < IMG) {
            size_t idx = (((size_t)(b * NW + (hh >> 3) * 32 + (ww >> 3))) * NTOK
                          + ((hh & 7) * 8 + (ww & 7))) * (size_t)CH + cb + c;
            v = Q[idx];
        }
        sm[p][c] = v;
    }
    __syncthreads();

    float w[9];
#pragma unroll
    for (int k = 0; k < 9; k++) w[k] = rw[(cb + c) * 9 + k];
    const float bias = rb[cb + c];

    const size_t sbase = (((size_t)(b * NW + win)) * NTOK) * CH + cb + c;
    for (int p = p0; p < 64; p += 4) {
        int py = p >> 3, px = p & 7;
        float acc = bias;
#pragma unroll
        for (int dy = 0; dy < 3; dy++)
#pragma unroll
            for (int dx = 0; dx < 3; dx++)
                acc = fmaf(sm[(py + dy) * 10 + (px + dx)][c], w[dy * 3 + dx], acc);
        S[sbase + (size_t)p * CH] += acc;
    }
}

// ---------------------------------------------------------------------------
// kernel_launch
// ---------------------------------------------------------------------------
extern "C" void kernel_launch(void* const* d_in, const int* in_sizes, int n_in,
                              void* d_out, int out_size)
{
    const float* x    = (const float*)d_in[0];
    const float* y    = (const float*)d_in[1];
    const float* mask = (const float*)d_in[2];
    const float* Wq   = (const float*)d_in[3];
    const float* bq   = (const float*)d_in[4];
    const float* Wk   = (const float*)d_in[5];
    const float* bk   = (const float*)d_in[6];
    const float* Wv   = (const float*)d_in[7];
    const float* bv   = (const float*)d_in[8];
    const float* rw   = (const float*)d_in[9];
    const float* rb   = (const float*)d_in[10];
    const float* Wp   = (const float*)d_in[11];
    const float* bp   = (const float*)d_in[12];
    float* out        = (float*)d_out;

    float *pQ, *pK, *pV, *pS;
    cudaGetSymbolAddress((void**)&pQ, g_Q);
    cudaGetSymbolAddress((void**)&pK, g_K);
    cudaGetSymbolAddress((void**)&pV, g_V);
    cudaGetSymbolAddress((void**)&pS, g_S);

    static bool attr_done = false;
    if (!attr_done) {
        cudaFuncSetAttribute(gemm_mma, cudaFuncAttributeMaxDynamicSharedMemorySize, GEMM_SMEM);
        cudaFuncSetAttribute(attn_mma, cudaFuncAttributeMaxDynamicSharedMemorySize, ATTN_SMEM);
        attr_done = true;
    }

    dim3 gg(2, MTOT / 128);   // (256/128, 262144/128)
    gemm_mma<<<gg, 256, GEMM_SMEM>>>(x, Wq, bq, pQ);
    gemm_mma<<<gg, 256, GEMM_SMEM>>>(y, Wk, bk, pK);
    gemm_mma<<<gg, 256, GEMM_SMEM>>>(x, Wv, bv, pV);

    attn_mma<<<dim3(4, BWIN), 128, ATTN_SMEM>>>(pQ, pK, pV, mask, pS);

    lepe_kernel<<<dim3(NW, BATCH, 4), 256>>>(pQ, rw, rb, pS);

    gemm_mma<<<gg, 256, GEMM_SMEM>>>(pS, Wp, bp, out);
}

// round 9
// speedup vs baseline: 1.3763x; 1.3367x over previous
#include <cuda_runtime.h>
#include <cuda_fp16.h>
#include <cstdint>

// Problem constants (fixed by setup_inputs)
#define BATCH 4
#define IMG 256
#define WS 8
#define NW 1024              // (256/8)^2
#define BWIN (BATCH * NW)    // 4096 windows
#define NTOK 64              // WS*WS
#define CH 256
#define HEADS 8
#define HD 32
#define MTOT (BWIN * NTOK)   // 262144 rows

// Scratch: Q/K/V in f16 (attn inputs), S in fp32 (lepe accumulates into it)
__device__ __half g_Q[(size_t)MTOT * CH];
__device__ __half g_K[(size_t)MTOT * CH];
__device__ __half g_V[(size_t)MTOT * CH];
__device__ float  g_S[(size_t)MTOT * CH];

// ---------------------------------------------------------------------------
// helpers (sm_75/80-generic; compute_103-safe)
// ---------------------------------------------------------------------------
__device__ __forceinline__ uint32_t smem_u32(const void* p) {
    uint32_t a;
    asm("{ .reg .u64 t; cvta.to.shared.u64 t, %1; cvt.u32.u64 %0, t; }" : "=r"(a) : "l"(p));
    return a;
}
__device__ __forceinline__ void mma_f16(float* d, const uint32_t* a, const uint32_t* b) {
    asm volatile(
        "mma.sync.aligned.m16n8k16.row.col.f32.f16.f16.f32 "
        "{%0,%1,%2,%3}, {%4,%5,%6,%7}, {%8,%9}, {%0,%1,%2,%3};"
        : "+f"(d[0]), "+f"(d[1]), "+f"(d[2]), "+f"(d[3])
        : "r"(a[0]), "r"(a[1]), "r"(a[2]), "r"(a[3]), "r"(b[0]), "r"(b[1]));
}
__device__ __forceinline__ void ldsm4(uint32_t* r, uint32_t addr) {
    asm volatile("ldmatrix.sync.aligned.m8n8.x4.shared.b16 {%0,%1,%2,%3}, [%4];"
        : "=r"(r[0]), "=r"(r[1]), "=r"(r[2]), "=r"(r[3]) : "r"(addr));
}
__device__ __forceinline__ void ldsm4t(uint32_t* r, uint32_t addr) {
    asm volatile("ldmatrix.sync.aligned.m8n8.x4.trans.shared.b16 {%0,%1,%2,%3}, [%4];"
        : "=r"(r[0]), "=r"(r[1]), "=r"(r[2]), "=r"(r[3]) : "r"(addr));
}
__device__ __forceinline__ uint32_t h2u(__half2 h) { return *reinterpret_cast<uint32_t*>(&h); }

// ---------------------------------------------------------------------------
// GEMM f16: C[M x 256] = A[M x 256] @ Wt^T + bias.  A fp32, tiles cvt to f16.
// Block 256 thr (8 warps 2x4), tile 128x128, K chunks of 64 (4 chunks),
// warp tile 64x32, mma m16n8k16, operand loads via ldmatrix.x4.
// smem stride 72 halves (144B): ldmatrix 8-row fetch covers all 32 banks.
// ---------------------------------------------------------------------------
#define KC 64
#define GSTR 72
#define GEMM_SMEM (2 * 2 * 128 * GSTR * 2)   // 73728 B

__device__ __forceinline__ void gemm_load_chunk(
    const float* Ap, const float* Bp, __half* Ad, __half* Bd, int t)
{
#pragma unroll
    for (int i = 0; i < 8; i++) {
        int linear = t + i * 256;          // 0..2047
        int row = linear >> 4;             // 0..127
        int c4 = (linear & 15) * 4;        // 0..60
        float4 va = *(const float4*)(Ap + (size_t)row * 256 + c4);
        float4 vb = *(const float4*)(Bp + (size_t)row * 256 + c4);
        uint2 pa, pb;
        pa.x = h2u(__floats2half2_rn(va.x, va.y));
        pa.y = h2u(__floats2half2_rn(va.z, va.w));
        pb.x = h2u(__floats2half2_rn(vb.x, vb.y));
        pb.y = h2u(__floats2half2_rn(vb.z, vb.w));
        *(uint2*)(Ad + row * GSTR + c4) = pa;
        *(uint2*)(Bd + row * GSTR + c4) = pb;
    }
}

template <typename OutT>
__global__ __launch_bounds__(256) void gemm_f16k(
    const float* __restrict__ A, const float* __restrict__ Wt,
    const float* __restrict__ bias, OutT* __restrict__ C)
{
    extern __shared__ __half hsm[];
    __half* Ah = hsm;                       // [2][128*GSTR]
    __half* Bh = hsm + 2 * 128 * GSTR;

    const int t = threadIdx.x, lane = t & 31, warp = t >> 5;
    const int wm = warp & 1, wn = warp >> 1;
    const int m0 = blockIdx.y * 128, n0 = blockIdx.x * 128;
    const int g = lane >> 2, tg = lane & 3;

    const uint32_t aBase = smem_u32(Ah), bBase = smem_u32(Bh);
    const int lmrow = lane & 15;            // A-ldmatrix row within 16
    const int lmk = (lane >> 4) << 3;       // A-ldmatrix k offset (0/8)
    const int bg2 = lane >> 3, bj = lane & 7;   // B-ldmatrix group / row

    float acc[4][4][4];
#pragma unroll
    for (int mi = 0; mi < 4; mi++)
#pragma unroll
        for (int ni = 0; ni < 4; ni++)
#pragma unroll
            for (int r = 0; r < 4; r++) acc[mi][ni][r] = 0.f;

    gemm_load_chunk(A + (size_t)m0 * 256, Wt + (size_t)n0 * 256, Ah, Bh, t);
    __syncthreads();

    for (int kc = 0; kc < 4; kc++) {
        if (kc < 3) {
            int buf = (kc + 1) & 1;
            gemm_load_chunk(A + (size_t)m0 * 256 + (kc + 1) * KC,
                            Wt + (size_t)n0 * 256 + (kc + 1) * KC,
                            Ah + buf * 128 * GSTR, Bh + buf * 128 * GSTR, t);
        }
        const uint32_t aB = aBase + (uint32_t)((kc & 1) * 128 * GSTR) * 2;
        const uint32_t bB = bBase + (uint32_t)((kc & 1) * 128 * GSTR) * 2;
#pragma unroll
        for (int ks = 0; ks < 4; ks++) {
            const int k0h = ks * 16;
            uint32_t a[4][4], b[4][2];
#pragma unroll
            for (int mi = 0; mi < 4; mi++)
                ldsm4(a[mi], aB + (uint32_t)((wm * 64 + mi * 16 + lmrow) * GSTR + k0h + lmk) * 2);
#pragma unroll
            for (int p = 0; p < 2; p++) {
                uint32_t r4[4];
                ldsm4(r4, bB + (uint32_t)((wn * 32 + p * 16 + ((bg2 >> 1) << 3) + bj) * GSTR
                                          + k0h + ((bg2 & 1) << 3)) * 2);
                b[2 * p][0] = r4[0]; b[2 * p][1] = r4[1];
                b[2 * p + 1][0] = r4[2]; b[2 * p + 1][1] = r4[3];
            }
#pragma unroll
            for (int mi = 0; mi < 4; mi++)
#pragma unroll
                for (int ni = 0; ni < 4; ni++)
                    mma_f16(acc[mi][ni], a[mi], b[ni]);
        }
        __syncthreads();
    }

    float bv[4][2];
#pragma unroll
    for (int ni = 0; ni < 4; ni++) {
        int col = n0 + wn * 32 + ni * 8 + 2 * tg;
        bv[ni][0] = __ldg(bias + col);
        bv[ni][1] = __ldg(bias + col + 1);
    }
#pragma unroll
    for (int mi = 0; mi < 4; mi++) {
        int r0 = m0 + wm * 64 + mi * 16 + g;
#pragma unroll
        for (int ni = 0; ni < 4; ni++) {
            int col = n0 + wn * 32 + ni * 8 + 2 * tg;
            if constexpr (sizeof(OutT) == 2) {
                *(__half2*)((__half*)C + (size_t)r0 * 256 + col) =
                    __floats2half2_rn(acc[mi][ni][0] + bv[ni][0], acc[mi][ni][1] + bv[ni][1]);
                *(__half2*)((__half*)C + (size_t)(r0 + 8) * 256 + col) =
                    __floats2half2_rn(acc[mi][ni][2] + bv[ni][0], acc[mi][ni][3] + bv[ni][1]);
            } else {
                *(float2*)((float*)C + (size_t)r0 * 256 + col) =
                    make_float2(acc[mi][ni][0] + bv[ni][0], acc[mi][ni][1] + bv[ni][1]);
                *(float2*)((float*)C + (size_t)(r0 + 8) * 256 + col) =
                    make_float2(acc[mi][ni][2] + bv[ni][0], acc[mi][ni][3] + bv[ni][1]);
            }
        }
    }
}

// ---------------------------------------------------------------------------
// Attention f16. Block = 128 thr (4 warps) per (window, head-pair).
// Q fragments from global f16 (warp-exclusive); K/V staged f16 in smem;
// QK + PV via m16n8k16 (V consumed with ldmatrix.trans — no transpose pass).
// Scale applied post-MMA in fp32; softmax fp32 in registers; P f16 per-warp.
// smem halves: Kh[64][72] | Vs[64][72] | P[4][32][72] = 36864 B -> 5 CTAs/SM.
// ---------------------------------------------------------------------------
#define AST 72
#define ATTN_SMEM ((2 * 64 * AST + 4 * 32 * AST) * 2)   // 36864 B

__global__ __launch_bounds__(128, 5) void attn_f16(
    const __half* __restrict__ Q, const __half* __restrict__ K,
    const __half* __restrict__ V, const float* __restrict__ mask,
    float* __restrict__ S)
{
    extern __shared__ __half asmh[];
    __half* Kh = asmh;                       // [64][AST]
    __half* Vs = asmh + 64 * AST;            // [64][AST]
    __half* Pp = asmh + 2 * 64 * AST;        // [4][32][AST]

    const int hp = blockIdx.x;      // head-pair 0..3
    const int b  = blockIdx.y;      // window 0..4095
    const int t = threadIdx.x, lane = t & 31, w = t >> 5;
    const int g = lane >> 2, tg = lane & 3;
    const int bg2 = lane >> 3, bj = lane & 7;
    const int lmrow = lane & 15, lmk = (lane >> 4) << 3;
    const size_t base = (size_t)b * NTOK * CH + hp * 64;
    const float scale = 0.17677669529663687f; // 32^-0.5

    // stage K, V head-pair slice (f16, direct copy)
#pragma unroll
    for (int i = 0; i < 8; i++) {
        int linear = i * 128 + t;          // 0..1023
        int row = linear >> 4;             // 0..63
        int c4 = (linear & 15) * 4;        // 0..60
        *(uint2*)(Kh + row * AST + c4) = *(const uint2*)(K + base + (size_t)row * 256 + c4);
        *(uint2*)(Vs + row * AST + c4) = *(const uint2*)(V + base + (size_t)row * 256 + c4);
    }
    __syncthreads();

    const int ch0 = (w >> 1) * 32;    // head channel offset within slice
    const int rbase = (w & 1) * 32;   // token-row base

    const __half* Qr[2][2];
#pragma unroll
    for (int mi = 0; mi < 2; mi++) {
        int r = rbase + mi * 16 + g;
        Qr[mi][0] = Q + base + (size_t)r * 256 + ch0;
        Qr[mi][1] = Q + base + (size_t)(r + 8) * 256 + ch0;
    }

    const uint32_t KhA = smem_u32(Kh), VsA = smem_u32(Vs);

    float acc[2][8][4];
#pragma unroll
    for (int mi = 0; mi < 2; mi++)
#pragma unroll
        for (int ni = 0; ni < 8; ni++)
#pragma unroll
            for (int r = 0; r < 4; r++) acc[mi][ni][r] = 0.f;

    // scores: 2 ksteps of k16 over HD=32
#pragma unroll
    for (int ks = 0; ks < 2; ks++) {
        uint32_t a[2][4], bb[8][2];
#pragma unroll
        for (int mi = 0; mi < 2; mi++) {
            a[mi][0] = *(const uint32_t*)(Qr[mi][0] + ks * 16 + 2 * tg);
            a[mi][1] = *(const uint32_t*)(Qr[mi][1] + ks * 16 + 2 * tg);
            a[mi][2] = *(const uint32_t*)(Qr[mi][0] + ks * 16 + 8 + 2 * tg);
            a[mi][3] = *(const uint32_t*)(Qr[mi][1] + ks * 16 + 8 + 2 * tg);
        }
#pragma unroll
        for (int p = 0; p < 4; p++) {
            uint32_t r4[4];
            ldsm4(r4, KhA + (uint32_t)((p * 16 + ((bg2 >> 1) << 3) + bj) * AST
                                       + ch0 + ks * 16 + ((bg2 & 1) << 3)) * 2);
            bb[2 * p][0] = r4[0]; bb[2 * p][1] = r4[1];
            bb[2 * p + 1][0] = r4[2]; bb[2 * p + 1][1] = r4[3];
        }
#pragma unroll
        for (int mi = 0; mi < 2; mi++)
#pragma unroll
            for (int ni = 0; ni < 8; ni++)
                mma_f16(acc[mi][ni], a[mi], bb[ni]);
    }

    // scale + mask + softmax (fp32, in place)
    const float* mp = mask + (size_t)(b & (NW - 1)) * NTOK * NTOK;
#pragma unroll
    for (int mi = 0; mi < 2; mi++) {
#pragma unroll
        for (int rh = 0; rh < 2; rh++) {
            const int row = rbase + mi * 16 + rh * 8 + g;
            const int o = rh * 2;
            float mx = -1e30f;
#pragma unroll
            for (int ni = 0; ni < 8; ni++) {
                float2 mv = *(const float2*)(mp + row * 64 + ni * 8 + 2 * tg);
                acc[mi][ni][o]     = fmaf(acc[mi][ni][o], scale, mv.x);
                acc[mi][ni][o + 1] = fmaf(acc[mi][ni][o + 1], scale, mv.y);
                mx = fmaxf(mx, fmaxf(acc[mi][ni][o], acc[mi][ni][o + 1]));
            }
            mx = fmaxf(mx, __shfl_xor_sync(0xffffffffu, mx, 1));
            mx = fmaxf(mx, __shfl_xor_sync(0xffffffffu, mx, 2));
            float sum = 0.f;
#pragma unroll
            for (int ni = 0; ni < 8; ni++) {
                acc[mi][ni][o]     = __expf(acc[mi][ni][o] - mx);
                acc[mi][ni][o + 1] = __expf(acc[mi][ni][o + 1] - mx);
                sum += acc[mi][ni][o] + acc[mi][ni][o + 1];
            }
            sum += __shfl_xor_sync(0xffffffffu, sum, 1);
            sum += __shfl_xor_sync(0xffffffffu, sum, 2);
            const float inv = 1.f / sum;
#pragma unroll
            for (int ni = 0; ni < 8; ni++) {
                acc[mi][ni][o]     *= inv;
                acc[mi][ni][o + 1] *= inv;
            }
        }
    }

    // store P (f16) into per-warp tile
    __half* Pw = Pp + w * 32 * AST;
#pragma unroll
    for (int mi = 0; mi < 2; mi++)
#pragma unroll
        for (int rh = 0; rh < 2; rh++) {
            const int rl = mi * 16 + rh * 8 + g;
#pragma unroll
            for (int ni = 0; ni < 8; ni++)
                *(__half2*)(Pw + rl * AST + ni * 8 + 2 * tg) =
                    __floats2half2_rn(acc[mi][ni][rh * 2], acc[mi][ni][rh * 2 + 1]);
        }
    __syncwarp();

    // O = P @ V : 4 ksteps of k16 over 64 tokens; V via ldmatrix.trans
    const uint32_t PwA = smem_u32(Pw);
    float acc2[2][4][4];
#pragma unroll
    for (int mi = 0; mi < 2; mi++)
#pragma unroll
        for (int ni = 0; ni < 4; ni++)
#pragma unroll
            for (int r = 0; r < 4; r++) acc2[mi][ni][r] = 0.f;

#pragma unroll
    for (int ks = 0; ks < 4; ks++) {
        uint32_t a[2][4], bb[4][2];
#pragma unroll
        for (int mi = 0; mi < 2; mi++)
            ldsm4(a[mi], PwA + (uint32_t)((mi * 16 + lmrow) * AST + ks * 16 + lmk) * 2);
#pragma unroll
        for (int p = 0; p < 2; p++) {
            uint32_t r4[4];
            int tok = ks * 16 + ((bg2 & 1) << 3) + bj;
            int chc = ch0 + p * 16 + ((bg2 >> 1) << 3);
            ldsm4t(r4, VsA + (uint32_t)(tok * AST + chc) * 2);
            bb[2 * p][0] = r4[0]; bb[2 * p][1] = r4[1];
            bb[2 * p + 1][0] = r4[2]; bb[2 * p + 1][1] = r4[3];
        }
#pragma unroll
        for (int mi = 0; mi < 2; mi++)
#pragma unroll
            for (int ni = 0; ni < 4; ni++)
                mma_f16(acc2[mi][ni], a[mi], bb[ni]);
    }

#pragma unroll
    for (int mi = 0; mi < 2; mi++) {
        const int row = rbase + mi * 16 + g;
#pragma unroll
        for (int ni = 0; ni < 4; ni++) {
            const int col = hp * 64 + ch0 + ni * 8 + 2 * tg;
            *(float2*)(S + (size_t)(b * NTOK + row) * 256 + col) =
                make_float2(acc2[mi][ni][0], acc2[mi][ni][1]);
            *(float2*)(S + (size_t)(b * NTOK + row + 8) * 256 + col) =
                make_float2(acc2[mi][ni][2], acc2[mi][ni][3]);
        }
    }
}

// ---------------------------------------------------------------------------
// LePE depthwise 3x3 conv on f16 Q, accumulated into fp32 S.
// ---------------------------------------------------------------------------
__global__ __launch_bounds__(256) void lepe_kernel(
    const __half* __restrict__ Q, const float* __restrict__ rw,
    const float* __restrict__ rb, float* __restrict__ S)
{
    __shared__ float sm[100][64];

    const int win = blockIdx.x;
    const int b = blockIdx.y;
    const int cb = blockIdx.z * 64;
    const int wr = win >> 5, wc = win & 31;
    const int hh0 = wr * 8, ww0 = wc * 8;
    const int t = threadIdx.x;
    const int c = t & 63, p0 = t >> 6;

    for (int p = p0; p < 100; p += 4) {
        int py = p / 10, px = p % 10;
        int hh = hh0 + py - 1, ww = ww0 + px - 1;
        float v = 0.f;
        if (hh >= 0 && hh < IMG && ww >= 0 && ww < IMG) {
            size_t idx = (((size_t)(b * NW + (hh >> 3) * 32 + (ww >> 3))) * NTOK
                          + ((hh & 7) * 8 + (ww & 7))) * (size_t)CH + cb + c;
            v = __half2float(Q[idx]);
        }
        sm[p][c] = v;
    }
    __syncthreads();

    float w[9];
#pragma unroll
    for (int k = 0; k < 9; k++) w[k] = rw[(cb + c) * 9 + k];
    const float bias = rb[cb + c];

    const size_t sbase = (((size_t)(b * NW + win)) * NTOK) * CH + cb + c;
    for (int p = p0; p < 64; p += 4) {
        int py = p >> 3, px = p & 7;
        float acc = bias;
#pragma unroll
        for (int dy = 0; dy < 3; dy++)
#pragma unroll
            for (int dx = 0; dx < 3; dx++)
                acc = fmaf(sm[(py + dy) * 10 + (px + dx)][c], w[dy * 3 + dx], acc);
        S[sbase + (size_t)p * CH] += acc;
    }
}

// ---------------------------------------------------------------------------
// kernel_launch
// ---------------------------------------------------------------------------
extern "C" void kernel_launch(void* const* d_in, const int* in_sizes, int n_in,
                              void* d_out, int out_size)
{
    const float* x    = (const float*)d_in[0];
    const float* y    = (const float*)d_in[1];
    const float* mask = (const float*)d_in[2];
    const float* Wq   = (const float*)d_in[3];
    const float* bq   = (const float*)d_in[4];
    const float* Wk   = (const float*)d_in[5];
    const float* bk   = (const float*)d_in[6];
    const float* Wv   = (const float*)d_in[7];
    const float* bv   = (const float*)d_in[8];
    const float* rw   = (const float*)d_in[9];
    const float* rb   = (const float*)d_in[10];
    const float* Wp   = (const float*)d_in[11];
    const float* bp   = (const float*)d_in[12];
    float* out        = (float*)d_out;

    __half *pQ, *pK, *pV;
    float *pS;
    cudaGetSymbolAddress((void**)&pQ, g_Q);
    cudaGetSymbolAddress((void**)&pK, g_K);
    cudaGetSymbolAddress((void**)&pV, g_V);
    cudaGetSymbolAddress((void**)&pS, g_S);

    static bool attr_done = false;
    if (!attr_done) {
        cudaFuncSetAttribute(gemm_f16k<__half>, cudaFuncAttributeMaxDynamicSharedMemorySize, GEMM_SMEM);
        cudaFuncSetAttribute(gemm_f16k<float>,  cudaFuncAttributeMaxDynamicSharedMemorySize, GEMM_SMEM);
        attr_done = true;
    }

    dim3 gg(2, MTOT / 128);   // (256/128, 262144/128)
    gemm_f16k<__half><<<gg, 256, GEMM_SMEM>>>(x, Wq, bq, pQ);
    gemm_f16k<__half><<<gg, 256, GEMM_SMEM>>>(y, Wk, bk, pK);
    gemm_f16k<__half><<<gg, 256, GEMM_SMEM>>>(x, Wv, bv, pV);

    attn_f16<<<dim3(4, BWIN), 128, ATTN_SMEM>>>(pQ, pK, pV, mask, pS);

    lepe_kernel<<<dim3(NW, BATCH, 4), 256>>>(pQ, rw, rb, pS);

    gemm_f16k<float><<<gg, 256, GEMM_SMEM>>>(pS, Wp, bp, out);
}

// round 10
// speedup vs baseline: 1.4924x; 1.0844x over previous
#include <cuda_runtime.h>
#include <cuda_fp16.h>
#include <cstdint>

// Problem constants (fixed by setup_inputs)
#define BATCH 4
#define IMG 256
#define WS 8
#define NW 1024              // (256/8)^2
#define BWIN (BATCH * NW)    // 4096 windows
#define NTOK 64              // WS*WS
#define CH 256
#define HEADS 8
#define HD 32
#define MTOT (BWIN * NTOK)   // 262144 rows

// Scratch (f16 pipeline)
__device__ __half g_xh[(size_t)MTOT * CH];
__device__ __half g_yh[(size_t)MTOT * CH];
__device__ __half g_Wqh[CH * CH];
__device__ __half g_Wkh[CH * CH];
__device__ __half g_Wvh[CH * CH];
__device__ __half g_Wph[CH * CH];
__device__ __half g_Q[(size_t)MTOT * CH];
__device__ __half g_K[(size_t)MTOT * CH];
__device__ __half g_V[(size_t)MTOT * CH];
__device__ __half g_O[(size_t)MTOT * CH];   // attn output
__device__ __half g_S[(size_t)MTOT * CH];   // attn + lepe (final GEMM input)

// ---------------------------------------------------------------------------
// helpers
// ---------------------------------------------------------------------------
__device__ __forceinline__ uint32_t smem_u32(const void* p) {
    uint32_t a;
    asm("{ .reg .u64 t; cvta.to.shared.u64 t, %1; cvt.u32.u64 %0, t; }" : "=r"(a) : "l"(p));
    return a;
}
__device__ __forceinline__ void mma_f16(float* d, const uint32_t* a, const uint32_t* b) {
    asm volatile(
        "mma.sync.aligned.m16n8k16.row.col.f32.f16.f16.f32 "
        "{%0,%1,%2,%3}, {%4,%5,%6,%7}, {%8,%9}, {%0,%1,%2,%3};"
        : "+f"(d[0]), "+f"(d[1]), "+f"(d[2]), "+f"(d[3])
        : "r"(a[0]), "r"(a[1]), "r"(a[2]), "r"(a[3]), "r"(b[0]), "r"(b[1]));
}
__device__ __forceinline__ void ldsm4(uint32_t* r, uint32_t addr) {
    asm volatile("ldmatrix.sync.aligned.m8n8.x4.shared.b16 {%0,%1,%2,%3}, [%4];"
        : "=r"(r[0]), "=r"(r[1]), "=r"(r[2]), "=r"(r[3]) : "r"(addr));
}
__device__ __forceinline__ void ldsm4t(uint32_t* r, uint32_t addr) {
    asm volatile("ldmatrix.sync.aligned.m8n8.x4.trans.shared.b16 {%0,%1,%2,%3}, [%4];"
        : "=r"(r[0]), "=r"(r[1]), "=r"(r[2]), "=r"(r[3]) : "r"(addr));
}
__device__ __forceinline__ uint32_t h2u(__half2 h) { return *reinterpret_cast<uint32_t*>(&h); }
__device__ __forceinline__ void cp16(void* dst, const void* src) {
    uint32_t d = smem_u32(dst);
    asm volatile("cp.async.cg.shared.global [%0], [%1], 16;" :: "r"(d), "l"(src));
}
#define CP_COMMIT() asm volatile("cp.async.commit_group;" ::: "memory")
#define CP_WAIT0()  asm volatile("cp.async.wait_group 0;" ::: "memory")

// ---------------------------------------------------------------------------
// fp32 -> f16 convert (streaming, 8 elem/thread)
// ---------------------------------------------------------------------------
__global__ __launch_bounds__(256) void cvt_f16(
    const float* __restrict__ in, __half* __restrict__ out)
{
    size_t i = ((size_t)blockIdx.x * 256 + threadIdx.x) * 8;
    float4 a = *(const float4*)(in + i);
    float4 b = *(const float4*)(in + i + 4);
    uint4 o;
    o.x = h2u(__floats2half2_rn(a.x, a.y));
    o.y = h2u(__floats2half2_rn(a.z, a.w));
    o.z = h2u(__floats2half2_rn(b.x, b.y));
    o.w = h2u(__floats2half2_rn(b.z, b.w));
    *(uint4*)(out + i) = o;
}

// ---------------------------------------------------------------------------
// GEMM pure f16 via cp.async + ldmatrix + mma.m16n8k16:
// C[M x 256] = A[M x 256] @ Wt^T + bias
// Block 256 thr (8 warps 2x4), tile 128x128, K chunks of 64, 2-stage buffer.
// smem stride 72 halves (144 B) -> ldmatrix conflict-free.
// ---------------------------------------------------------------------------
#define KC 64
#define GSTR 72
#define GEMM_SMEM (2 * 2 * 128 * GSTR * 2)   // 73728 B

__device__ __forceinline__ void load_chunk_async(
    const __half* Ap, const __half* Bp, __half* Ad, __half* Bd, int t)
{
    // 128 rows x 8 chunks of 16B per operand = 1024 cp; 256 thr -> 4 each
    const int c16 = (t & 7) * 8;     // half offset within row
    const int row0 = t >> 3;         // 0..31
#pragma unroll
    for (int i = 0; i < 4; i++) {
        int row = row0 + i * 32;
        cp16(Ad + row * GSTR + c16, Ap + (size_t)row * 256 + c16);
        cp16(Bd + row * GSTR + c16, Bp + (size_t)row * 256 + c16);
    }
}

template <typename OutT>
__global__ __launch_bounds__(256) void gemm_f16k(
    const __half* __restrict__ A, const __half* __restrict__ Wt,
    const float* __restrict__ bias, OutT* __restrict__ C)
{
    extern __shared__ __half hsm[];
    __half* Ah = hsm;                       // [2][128*GSTR]
    __half* Bh = hsm + 2 * 128 * GSTR;

    const int t = threadIdx.x, lane = t & 31, warp = t >> 5;
    const int wm = warp & 1, wn = warp >> 1;
    const int m0 = blockIdx.y * 128, n0 = blockIdx.x * 128;
    const int g = lane >> 2, tg = lane & 3;

    const uint32_t aBase = smem_u32(Ah), bBase = smem_u32(Bh);
    const int lmrow = lane & 15, lmk = (lane >> 4) << 3;
    const int bg2 = lane >> 3, bj = lane & 7;

    float acc[4][4][4];
#pragma unroll
    for (int mi = 0; mi < 4; mi++)
#pragma unroll
        for (int ni = 0; ni < 4; ni++)
#pragma unroll
            for (int r = 0; r < 4; r++) acc[mi][ni][r] = 0.f;

    load_chunk_async(A + (size_t)m0 * 256, Wt + (size_t)n0 * 256, Ah, Bh, t);
    CP_COMMIT();

    for (int kc = 0; kc < 4; kc++) {
        CP_WAIT0();
        __syncthreads();
        if (kc < 3) {
            int buf = (kc + 1) & 1;
            load_chunk_async(A + (size_t)m0 * 256 + (kc + 1) * KC,
                             Wt + (size_t)n0 * 256 + (kc + 1) * KC,
                             Ah + buf * 128 * GSTR, Bh + buf * 128 * GSTR, t);
            CP_COMMIT();
        }
        const uint32_t aB = aBase + (uint32_t)((kc & 1) * 128 * GSTR) * 2;
        const uint32_t bB = bBase + (uint32_t)((kc & 1) * 128 * GSTR) * 2;
#pragma unroll
        for (int ks = 0; ks < 4; ks++) {
            const int k0h = ks * 16;
            uint32_t a[4][4], b[4][2];
#pragma unroll
            for (int mi = 0; mi < 4; mi++)
                ldsm4(a[mi], aB + (uint32_t)((wm * 64 + mi * 16 + lmrow) * GSTR + k0h + lmk) * 2);
#pragma unroll
            for (int p = 0; p < 2; p++) {
                uint32_t r4[4];
                ldsm4(r4, bB + (uint32_t)((wn * 32 + p * 16 + ((bg2 >> 1) << 3) + bj) * GSTR
                                          + k0h + ((bg2 & 1) << 3)) * 2);
                b[2 * p][0] = r4[0]; b[2 * p][1] = r4[1];
                b[2 * p + 1][0] = r4[2]; b[2 * p + 1][1] = r4[3];
            }
#pragma unroll
            for (int mi = 0; mi < 4; mi++)
#pragma unroll
                for (int ni = 0; ni < 4; ni++)
                    mma_f16(acc[mi][ni], a[mi], b[ni]);
        }
        __syncthreads();
    }

    float bv[4][2];
#pragma unroll
    for (int ni = 0; ni < 4; ni++) {
        int col = n0 + wn * 32 + ni * 8 + 2 * tg;
        bv[ni][0] = __ldg(bias + col);
        bv[ni][1] = __ldg(bias + col + 1);
    }
#pragma unroll
    for (int mi = 0; mi < 4; mi++) {
        int r0 = m0 + wm * 64 + mi * 16 + g;
#pragma unroll
        for (int ni = 0; ni < 4; ni++) {
            int col = n0 + wn * 32 + ni * 8 + 2 * tg;
            if constexpr (sizeof(OutT) == 2) {
                *(__half2*)((__half*)C + (size_t)r0 * 256 + col) =
                    __floats2half2_rn(acc[mi][ni][0] + bv[ni][0], acc[mi][ni][1] + bv[ni][1]);
                *(__half2*)((__half*)C + (size_t)(r0 + 8) * 256 + col) =
                    __floats2half2_rn(acc[mi][ni][2] + bv[ni][0], acc[mi][ni][3] + bv[ni][1]);
            } else {
                *(float2*)((float*)C + (size_t)r0 * 256 + col) =
                    make_float2(acc[mi][ni][0] + bv[ni][0], acc[mi][ni][1] + bv[ni][1]);
                *(float2*)((float*)C + (size_t)(r0 + 8) * 256 + col) =
                    make_float2(acc[mi][ni][2] + bv[ni][0], acc[mi][ni][3] + bv[ni][1]);
            }
        }
    }
}

// ---------------------------------------------------------------------------
// Attention f16 (round-9 structure), writes O in f16.
// ---------------------------------------------------------------------------
#define AST 72
#define ATTN_SMEM ((2 * 64 * AST + 4 * 32 * AST) * 2)   // 36864 B

__global__ __launch_bounds__(128, 5) void attn_f16(
    const __half* __restrict__ Q, const __half* __restrict__ K,
    const __half* __restrict__ V, const float* __restrict__ mask,
    __half* __restrict__ O)
{
    extern __shared__ __half asmh[];
    __half* Kh = asmh;                       // [64][AST]
    __half* Vs = asmh + 64 * AST;            // [64][AST]
    __half* Pp = asmh + 2 * 64 * AST;        // [4][32][AST]

    const int hp = blockIdx.x;
    const int b  = blockIdx.y;
    const int t = threadIdx.x, lane = t & 31, w = t >> 5;
    const int g = lane >> 2, tg = lane & 3;
    const int bg2 = lane >> 3, bj = lane & 7;
    const int lmrow = lane & 15, lmk = (lane >> 4) << 3;
    const size_t base = (size_t)b * NTOK * CH + hp * 64;
    const float scale = 0.17677669529663687f;

#pragma unroll
    for (int i = 0; i < 8; i++) {
        int linear = i * 128 + t;
        int row = linear >> 4;
        int c4 = (linear & 15) * 4;
        *(uint2*)(Kh + row * AST + c4) = *(const uint2*)(K + base + (size_t)row * 256 + c4);
        *(uint2*)(Vs + row * AST + c4) = *(const uint2*)(V + base + (size_t)row * 256 + c4);
    }
    __syncthreads();

    const int ch0 = (w >> 1) * 32;
    const int rbase = (w & 1) * 32;

    const __half* Qr[2][2];
#pragma unroll
    for (int mi = 0; mi < 2; mi++) {
        int r = rbase + mi * 16 + g;
        Qr[mi][0] = Q + base + (size_t)r * 256 + ch0;
        Qr[mi][1] = Q + base + (size_t)(r + 8) * 256 + ch0;
    }

    const uint32_t KhA = smem_u32(Kh), VsA = smem_u32(Vs);

    float acc[2][8][4];
#pragma unroll
    for (int mi = 0; mi < 2; mi++)
#pragma unroll
        for (int ni = 0; ni < 8; ni++)
#pragma unroll
            for (int r = 0; r < 4; r++) acc[mi][ni][r] = 0.f;

#pragma unroll
    for (int ks = 0; ks < 2; ks++) {
        uint32_t a[2][4], bb[8][2];
#pragma unroll
        for (int mi = 0; mi < 2; mi++) {
            a[mi][0] = *(const uint32_t*)(Qr[mi][0] + ks * 16 + 2 * tg);
            a[mi][1] = *(const uint32_t*)(Qr[mi][1] + ks * 16 + 2 * tg);
            a[mi][2] = *(const uint32_t*)(Qr[mi][0] + ks * 16 + 8 + 2 * tg);
            a[mi][3] = *(const uint32_t*)(Qr[mi][1] + ks * 16 + 8 + 2 * tg);
        }
#pragma unroll
        for (int p = 0; p < 4; p++) {
            uint32_t r4[4];
            ldsm4(r4, KhA + (uint32_t)((p * 16 + ((bg2 >> 1) << 3) + bj) * AST
                                       + ch0 + ks * 16 + ((bg2 & 1) << 3)) * 2);
            bb[2 * p][0] = r4[0]; bb[2 * p][1] = r4[1];
            bb[2 * p + 1][0] = r4[2]; bb[2 * p + 1][1] = r4[3];
        }
#pragma unroll
        for (int mi = 0; mi < 2; mi++)
#pragma unroll
            for (int ni = 0; ni < 8; ni++)
                mma_f16(acc[mi][ni], a[mi], bb[ni]);
    }

    const float* mp = mask + (size_t)(b & (NW - 1)) * NTOK * NTOK;
#pragma unroll
    for (int mi = 0; mi < 2; mi++) {
#pragma unroll
        for (int rh = 0; rh < 2; rh++) {
            const int row = rbase + mi * 16 + rh * 8 + g;
            const int o = rh * 2;
            float mx = -1e30f;
#pragma unroll
            for (int ni = 0; ni < 8; ni++) {
                float2 mv = *(const float2*)(mp + row * 64 + ni * 8 + 2 * tg);
                acc[mi][ni][o]     = fmaf(acc[mi][ni][o], scale, mv.x);
                acc[mi][ni][o + 1] = fmaf(acc[mi][ni][o + 1], scale, mv.y);
                mx = fmaxf(mx, fmaxf(acc[mi][ni][o], acc[mi][ni][o + 1]));
            }
            mx = fmaxf(mx, __shfl_xor_sync(0xffffffffu, mx, 1));
            mx = fmaxf(mx, __shfl_xor_sync(0xffffffffu, mx, 2));
            float sum = 0.f;
#pragma unroll
            for (int ni = 0; ni < 8; ni++) {
                acc[mi][ni][o]     = __expf(acc[mi][ni][o] - mx);
                acc[mi][ni][o + 1] = __expf(acc[mi][ni][o + 1] - mx);
                sum += acc[mi][ni][o] + acc[mi][ni][o + 1];
            }
            sum += __shfl_xor_sync(0xffffffffu, sum, 1);
            sum += __shfl_xor_sync(0xffffffffu, sum, 2);
            const float inv = 1.f / sum;
#pragma unroll
            for (int ni = 0; ni < 8; ni++) {
                acc[mi][ni][o]     *= inv;
                acc[mi][ni][o + 1] *= inv;
            }
        }
    }

    __half* Pw = Pp + w * 32 * AST;
#pragma unroll
    for (int mi = 0; mi < 2; mi++)
#pragma unroll
        for (int rh = 0; rh < 2; rh++) {
            const int rl = mi * 16 + rh * 8 + g;
#pragma unroll
            for (int ni = 0; ni < 8; ni++)
                *(__half2*)(Pw + rl * AST + ni * 8 + 2 * tg) =
                    __floats2half2_rn(acc[mi][ni][rh * 2], acc[mi][ni][rh * 2 + 1]);
        }
    __syncwarp();

    const uint32_t PwA = smem_u32(Pw);
    float acc2[2][4][4];
#pragma unroll
    for (int mi = 0; mi < 2; mi++)
#pragma unroll
        for (int ni = 0; ni < 4; ni++)
#pragma unroll
            for (int r = 0; r < 4; r++) acc2[mi][ni][r] = 0.f;

#pragma unroll
    for (int ks = 0; ks < 4; ks++) {
        uint32_t a[2][4], bb[4][2];
#pragma unroll
        for (int mi = 0; mi < 2; mi++)
            ldsm4(a[mi], PwA + (uint32_t)((mi * 16 + lmrow) * AST + ks * 16 + lmk) * 2);
#pragma unroll
        for (int p = 0; p < 2; p++) {
            uint32_t r4[4];
            int tok = ks * 16 + ((bg2 & 1) << 3) + bj;
            int chc = ch0 + p * 16 + ((bg2 >> 1) << 3);
            ldsm4t(r4, VsA + (uint32_t)(tok * AST + chc) * 2);
            bb[2 * p][0] = r4[0]; bb[2 * p][1] = r4[1];
            bb[2 * p + 1][0] = r4[2]; bb[2 * p + 1][1] = r4[3];
        }
#pragma unroll
        for (int mi = 0; mi < 2; mi++)
#pragma unroll
            for (int ni = 0; ni < 4; ni++)
                mma_f16(acc2[mi][ni], a[mi], bb[ni]);
    }

#pragma unroll
    for (int mi = 0; mi < 2; mi++) {
        const int row = rbase + mi * 16 + g;
#pragma unroll
        for (int ni = 0; ni < 4; ni++) {
            const int col = hp * 64 + ch0 + ni * 8 + 2 * tg;
            *(__half2*)(O + (size_t)(b * NTOK + row) * 256 + col) =
                __floats2half2_rn(acc2[mi][ni][0], acc2[mi][ni][1]);
            *(__half2*)(O + (size_t)(b * NTOK + row + 8) * 256 + col) =
                __floats2half2_rn(acc2[mi][ni][2], acc2[mi][ni][3]);
        }
    }
}

// ---------------------------------------------------------------------------
// LePE depthwise 3x3 conv on f16 Q; adds attn O; writes S (f16, no rmw).
// ---------------------------------------------------------------------------
__global__ __launch_bounds__(256) void lepe_kernel(
    const __half* __restrict__ Q, const float* __restrict__ rw,
    const float* __restrict__ rb, const __half* __restrict__ O,
    __half* __restrict__ S)
{
    __shared__ float sm[100][64];

    const int win = blockIdx.x;
    const int b = blockIdx.y;
    const int cb = blockIdx.z * 64;
    const int wr = win >> 5, wc = win & 31;
    const int hh0 = wr * 8, ww0 = wc * 8;
    const int t = threadIdx.x;
    const int c = t & 63, p0 = t >> 6;

    for (int p = p0; p < 100; p += 4) {
        int py = p / 10, px = p % 10;
        int hh = hh0 + py - 1, ww = ww0 + px - 1;
        float v = 0.f;
        if (hh >= 0 && hh < IMG && ww >= 0 && ww < IMG) {
            size_t idx = (((size_t)(b * NW + (hh >> 3) * 32 + (ww >> 3))) * NTOK
                          + ((hh & 7) * 8 + (ww & 7))) * (size_t)CH + cb + c;
            v = __half2float(Q[idx]);
        }
        sm[p][c] = v;
    }
    __syncthreads();

    float w[9];
#pragma unroll
    for (int k = 0; k < 9; k++) w[k] = rw[(cb + c) * 9 + k];
    const float bias = rb[cb + c];

    const size_t sbase = (((size_t)(b * NW + win)) * NTOK) * CH + cb + c;
    for (int p = p0; p < 64; p += 4) {
        int py = p >> 3, px = p & 7;
        float acc = bias;
#pragma unroll
        for (int dy = 0; dy < 3; dy++)
#pragma unroll
            for (int dx = 0; dx < 3; dx++)
                acc = fmaf(sm[(py + dy) * 10 + (px + dx)][c], w[dy * 3 + dx], acc);
        size_t idx = sbase + (size_t)p * CH;
        S[idx] = __float2half(acc + __half2float(O[idx]));
    }
}

// ---------------------------------------------------------------------------
// kernel_launch
// ---------------------------------------------------------------------------
extern "C" void kernel_launch(void* const* d_in, const int* in_sizes, int n_in,
                              void* d_out, int out_size)
{
    const float* x    = (const float*)d_in[0];
    const float* y    = (const float*)d_in[1];
    const float* mask = (const float*)d_in[2];
    const float* Wq   = (const float*)d_in[3];
    const float* bq   = (const float*)d_in[4];
    const float* Wk   = (const float*)d_in[5];
    const float* bk   = (const float*)d_in[6];
    const float* Wv   = (const float*)d_in[7];
    const float* bv   = (const float*)d_in[8];
    const float* rw   = (const float*)d_in[9];
    const float* rb   = (const float*)d_in[10];
    const float* Wp   = (const float*)d_in[11];
    const float* bp   = (const float*)d_in[12];
    float* out        = (float*)d_out;

    __half *pxh, *pyh, *pWq, *pWk, *pWv, *pWp, *pQ, *pK, *pV, *pO, *pS;
    cudaGetSymbolAddress((void**)&pxh, g_xh);
    cudaGetSymbolAddress((void**)&pyh, g_yh);
    cudaGetSymbolAddress((void**)&pWq, g_Wqh);
    cudaGetSymbolAddress((void**)&pWk, g_Wkh);
    cudaGetSymbolAddress((void**)&pWv, g_Wvh);
    cudaGetSymbolAddress((void**)&pWp, g_Wph);
    cudaGetSymbolAddress((void**)&pQ, g_Q);
    cudaGetSymbolAddress((void**)&pK, g_K);
    cudaGetSymbolAddress((void**)&pV, g_V);
    cudaGetSymbolAddress((void**)&pO, g_O);
    cudaGetSymbolAddress((void**)&pS, g_S);

    static bool attr_done = false;
    if (!attr_done) {
        cudaFuncSetAttribute(gemm_f16k<__half>, cudaFuncAttributeMaxDynamicSharedMemorySize, GEMM_SMEM);
        cudaFuncSetAttribute(gemm_f16k<float>,  cudaFuncAttributeMaxDynamicSharedMemorySize, GEMM_SMEM);
        attr_done = true;
    }

    const int NBIG = (int)((size_t)MTOT * CH / (256 * 8));   // 32768 blocks
    const int NW2 = CH * CH / (256 * 8);                      // 32 blocks
    cvt_f16<<<NBIG, 256>>>(x, pxh);
    cvt_f16<<<NBIG, 256>>>(y, pyh);
    cvt_f16<<<NW2, 256>>>(Wq, pWq);
    cvt_f16<<<NW2, 256>>>(Wk, pWk);
    cvt_f16<<<NW2, 256>>>(Wv, pWv);
    cvt_f16<<<NW2, 256>>>(Wp, pWp);

    dim3 gg(2, MTOT / 128);
    gemm_f16k<__half><<<gg, 256, GEMM_SMEM>>>(pxh, pWq, bq, pQ);
    gemm_f16k<__half><<<gg, 256, GEMM_SMEM>>>(pyh, pWk, bk, pK);
    gemm_f16k<__half><<<gg, 256, GEMM_SMEM>>>(pxh, pWv, bv, pV);

    attn_f16<<<dim3(4, BWIN), 128, ATTN_SMEM>>>(pQ, pK, pV, mask, pO);

    lepe_kernel<<<dim3(NW, BATCH, 4), 256>>>(pQ, rw, rb, pO, pS);

    gemm_f16k<float><<<gg, 256, GEMM_SMEM>>>(pS, pWp, bp, out);
}

// round 11
// speedup vs baseline: 1.6256x; 1.0892x over previous
#include <cuda_runtime.h>
#include <cuda_fp16.h>
#include <cstdint>

// Problem constants (fixed by setup_inputs)
#define BATCH 4
#define IMG 256
#define WS 8
#define NW 1024              // (256/8)^2
#define BWIN (BATCH * NW)    // 4096 windows
#define NTOK 64              // WS*WS
#define CH 256
#define HEADS 8
#define HD 32
#define MTOT (BWIN * NTOK)   // 262144 rows

// Scratch (f16 pipeline)
__device__ __half g_xh[(size_t)MTOT * CH];
__device__ __half g_yh[(size_t)MTOT * CH];
__device__ __half g_Wqh[CH * CH];
__device__ __half g_Wkh[CH * CH];
__device__ __half g_Wvh[CH * CH];
__device__ __half g_Wph[CH * CH];
__device__ __half g_Q[(size_t)MTOT * CH];
__device__ __half g_K[(size_t)MTOT * CH];
__device__ __half g_V[(size_t)MTOT * CH];
__device__ __half g_S[(size_t)MTOT * CH];   // attn + lepe (final GEMM input)

// ---------------------------------------------------------------------------
// helpers
// ---------------------------------------------------------------------------
__device__ __forceinline__ uint32_t smem_u32(const void* p) {
    uint32_t a;
    asm("{ .reg .u64 t; cvta.to.shared.u64 t, %1; cvt.u32.u64 %0, t; }" : "=r"(a) : "l"(p));
    return a;
}
__device__ __forceinline__ void mma_f16(float* d, const uint32_t* a, const uint32_t* b) {
    asm volatile(
        "mma.sync.aligned.m16n8k16.row.col.f32.f16.f16.f32 "
        "{%0,%1,%2,%3}, {%4,%5,%6,%7}, {%8,%9}, {%0,%1,%2,%3};"
        : "+f"(d[0]), "+f"(d[1]), "+f"(d[2]), "+f"(d[3])
        : "r"(a[0]), "r"(a[1]), "r"(a[2]), "r"(a[3]), "r"(b[0]), "r"(b[1]));
}
__device__ __forceinline__ void ldsm4(uint32_t* r, uint32_t addr) {
    asm volatile("ldmatrix.sync.aligned.m8n8.x4.shared.b16 {%0,%1,%2,%3}, [%4];"
        : "=r"(r[0]), "=r"(r[1]), "=r"(r[2]), "=r"(r[3]) : "r"(addr));
}
__device__ __forceinline__ void ldsm4t(uint32_t* r, uint32_t addr) {
    asm volatile("ldmatrix.sync.aligned.m8n8.x4.trans.shared.b16 {%0,%1,%2,%3}, [%4];"
        : "=r"(r[0]), "=r"(r[1]), "=r"(r[2]), "=r"(r[3]) : "r"(addr));
}
__device__ __forceinline__ uint32_t h2u(__half2 h) { return *reinterpret_cast<uint32_t*>(&h); }
__device__ __forceinline__ void cp16(void* dst, const void* src) {
    uint32_t d = smem_u32(dst);
    asm volatile("cp.async.cg.shared.global [%0], [%1], 16;" :: "r"(d), "l"(src));
}
__device__ __forceinline__ void cp8(void* dst, const void* src) {
    uint32_t d = smem_u32(dst);
    asm volatile("cp.async.ca.shared.global [%0], [%1], 8;" :: "r"(d), "l"(src));
}
#define CP_COMMIT() asm volatile("cp.async.commit_group;" ::: "memory")
#define CP_WAIT0()  asm volatile("cp.async.wait_group 0;" ::: "memory")

// ---------------------------------------------------------------------------
// fp32 -> f16 convert (streaming, 8 elem/thread)
// ---------------------------------------------------------------------------
__global__ __launch_bounds__(256) void cvt_f16(
    const float* __restrict__ in, __half* __restrict__ out)
{
    size_t i = ((size_t)blockIdx.x * 256 + threadIdx.x) * 8;
    float4 a = *(const float4*)(in + i);
    float4 b = *(const float4*)(in + i + 4);
    uint4 o;
    o.x = h2u(__floats2half2_rn(a.x, a.y));
    o.y = h2u(__floats2half2_rn(a.z, a.w));
    o.z = h2u(__floats2half2_rn(b.x, b.y));
    o.w = h2u(__floats2half2_rn(b.z, b.w));
    *(uint4*)(out + i) = o;
}

// ---------------------------------------------------------------------------
// GEMM pure f16 via cp.async + ldmatrix + mma.m16n8k16 (round-10 structure)
// ---------------------------------------------------------------------------
#define KC 64
#define GSTR 72
#define GEMM_SMEM (2 * 2 * 128 * GSTR * 2)   // 73728 B

__device__ __forceinline__ void load_chunk_async(
    const __half* Ap, const __half* Bp, __half* Ad, __half* Bd, int t)
{
    const int c16 = (t & 7) * 8;
    const int row0 = t >> 3;
#pragma unroll
    for (int i = 0; i < 4; i++) {
        int row = row0 + i * 32;
        cp16(Ad + row * GSTR + c16, Ap + (size_t)row * 256 + c16);
        cp16(Bd + row * GSTR + c16, Bp + (size_t)row * 256 + c16);
    }
}

template <typename OutT>
__global__ __launch_bounds__(256) void gemm_f16k(
    const __half* __restrict__ A, const __half* __restrict__ Wt,
    const float* __restrict__ bias, OutT* __restrict__ C)
{
    extern __shared__ __half hsm[];
    __half* Ah = hsm;
    __half* Bh = hsm + 2 * 128 * GSTR;

    const int t = threadIdx.x, lane = t & 31, warp = t >> 5;
    const int wm = warp & 1, wn = warp >> 1;
    const int m0 = blockIdx.y * 128, n0 = blockIdx.x * 128;
    const int g = lane >> 2, tg = lane & 3;

    const uint32_t aBase = smem_u32(Ah), bBase = smem_u32(Bh);
    const int lmrow = lane & 15, lmk = (lane >> 4) << 3;
    const int bg2 = lane >> 3, bj = lane & 7;

    float acc[4][4][4];
#pragma unroll
    for (int mi = 0; mi < 4; mi++)
#pragma unroll
        for (int ni = 0; ni < 4; ni++)
#pragma unroll
            for (int r = 0; r < 4; r++) acc[mi][ni][r] = 0.f;

    load_chunk_async(A + (size_t)m0 * 256, Wt + (size_t)n0 * 256, Ah, Bh, t);
    CP_COMMIT();

    for (int kc = 0; kc < 4; kc++) {
        CP_WAIT0();
        __syncthreads();
        if (kc < 3) {
            int buf = (kc + 1) & 1;
            load_chunk_async(A + (size_t)m0 * 256 + (kc + 1) * KC,
                             Wt + (size_t)n0 * 256 + (kc + 1) * KC,
                             Ah + buf * 128 * GSTR, Bh + buf * 128 * GSTR, t);
            CP_COMMIT();
        }
        const uint32_t aB = aBase + (uint32_t)((kc & 1) * 128 * GSTR) * 2;
        const uint32_t bB = bBase + (uint32_t)((kc & 1) * 128 * GSTR) * 2;
#pragma unroll
        for (int ks = 0; ks < 4; ks++) {
            const int k0h = ks * 16;
            uint32_t a[4][4], b[4][2];
#pragma unroll
            for (int mi = 0; mi < 4; mi++)
                ldsm4(a[mi], aB + (uint32_t)((wm * 64 + mi * 16 + lmrow) * GSTR + k0h + lmk) * 2);
#pragma unroll
            for (int p = 0; p < 2; p++) {
                uint32_t r4[4];
                ldsm4(r4, bB + (uint32_t)((wn * 32 + p * 16 + ((bg2 >> 1) << 3) + bj) * GSTR
                                          + k0h + ((bg2 & 1) << 3)) * 2);
                b[2 * p][0] = r4[0]; b[2 * p][1] = r4[1];
                b[2 * p + 1][0] = r4[2]; b[2 * p + 1][1] = r4[3];
            }
#pragma unroll
            for (int mi = 0; mi < 4; mi++)
#pragma unroll
                for (int ni = 0; ni < 4; ni++)
                    mma_f16(acc[mi][ni], a[mi], b[ni]);
        }
        __syncthreads();
    }

    float bv[4][2];
#pragma unroll
    for (int ni = 0; ni < 4; ni++) {
        int col = n0 + wn * 32 + ni * 8 + 2 * tg;
        bv[ni][0] = __ldg(bias + col);
        bv[ni][1] = __ldg(bias + col + 1);
    }
#pragma unroll
    for (int mi = 0; mi < 4; mi++) {
        int r0 = m0 + wm * 64 + mi * 16 + g;
#pragma unroll
        for (int ni = 0; ni < 4; ni++) {
            int col = n0 + wn * 32 + ni * 8 + 2 * tg;
            if constexpr (sizeof(OutT) == 2) {
                *(__half2*)((__half*)C + (size_t)r0 * 256 + col) =
                    __floats2half2_rn(acc[mi][ni][0] + bv[ni][0], acc[mi][ni][1] + bv[ni][1]);
                *(__half2*)((__half*)C + (size_t)(r0 + 8) * 256 + col) =
                    __floats2half2_rn(acc[mi][ni][2] + bv[ni][0], acc[mi][ni][3] + bv[ni][1]);
            } else {
                *(float2*)((float*)C + (size_t)r0 * 256 + col) =
                    make_float2(acc[mi][ni][0] + bv[ni][0], acc[mi][ni][1] + bv[ni][1]);
                *(float2*)((float*)C + (size_t)(r0 + 8) * 256 + col) =
                    make_float2(acc[mi][ni][2] + bv[ni][0], acc[mi][ni][3] + bv[ni][1]);
            }
        }
    }
}

// ---------------------------------------------------------------------------
// Attention f16 + fused LePE. Block = 128 thr per (window, head-pair).
// Halo Q (10x10 x 64ch) + conv weights prefetched via cp.async at kernel
// start (dedicated smem regions) — fully overlapped with QK/softmax/PV.
// O stays in fp32 regs; S = O + lepe written once (f16).
// smem: Kh[64][72] | Vs[64][72] | P[4][32][72] | halo[100][68] | w[576]+b[64]
//       = 53024 B -> 4 CTAs/SM.
// ---------------------------------------------------------------------------
#define AST 72
#define HSTR 68
#define ATTN_SMEM 53024

__global__ __launch_bounds__(128, 4) void attn_lepe(
    const __half* __restrict__ Q, const __half* __restrict__ K,
    const __half* __restrict__ V, const float* __restrict__ mask,
    const float* __restrict__ rw, const float* __restrict__ rb,
    __half* __restrict__ S)
{
    extern __shared__ __half asmh[];
    __half* Kh   = asmh;                 // [64][AST]
    __half* Vs   = asmh + 4608;          // [64][AST]
    __half* Pp   = asmh + 9216;          // [4][32][AST]
    __half* Halo = asmh + 18432;         // [100][HSTR]
    float*  Wsm  = (float*)(asmh + 25232);  // [576]
    float*  Bsm  = Wsm + 576;               // [64]

    const int hp = blockIdx.x;
    const int b  = blockIdx.y;
    const int t = threadIdx.x, lane = t & 31, w = t >> 5;
    const int g = lane >> 2, tg = lane & 3;
    const int bg2 = lane >> 3, bj = lane & 7;
    const int lmrow = lane & 15, lmk = (lane >> 4) << 3;
    const size_t base = (size_t)b * NTOK * CH + hp * 64;
    const float scale = 0.17677669529663687f;

    // ---- prefetch conv weights + halo Q (async; consumed after PV) ----
    const int bi = b >> 10, win = b & 1023;
    const int hh0 = (win >> 5) * 8, ww0 = (win & 31) * 8;
#pragma unroll
    for (int i = t; i < 160; i += 128) {
        if (i < 144) cp16(Wsm + i * 4, rw + (size_t)hp * 576 + i * 4);
        else         cp16(Bsm + (i - 144) * 4, rb + hp * 64 + (i - 144) * 4);
    }
#pragma unroll
    for (int i = 0; i < 13; i++) {
        int linear = t + i * 128;
        if (linear < 1600) {
            int p = linear >> 4, c4 = (linear & 15) * 4;
            int py = p / 10, px = p % 10;
            int hh = hh0 + py - 1, ww = ww0 + px - 1;
            __half* dst = Halo + p * HSTR + c4;
            if (hh >= 0 && hh < IMG && ww >= 0 && ww < IMG) {
                size_t src = ((size_t)(bi * NW + (hh >> 3) * 32 + (ww >> 3)) * NTOK
                              + ((hh & 7) * 8 + (ww & 7))) * CH + hp * 64 + c4;
                cp8(dst, Q + src);
            } else {
                *(uint2*)dst = make_uint2(0u, 0u);
            }
        }
    }
    CP_COMMIT();

    // ---- stage K, V head-pair slice ----
#pragma unroll
    for (int i = 0; i < 8; i++) {
        int linear = i * 128 + t;
        int row = linear >> 4;
        int c4 = (linear & 15) * 4;
        *(uint2*)(Kh + row * AST + c4) = *(const uint2*)(K + base + (size_t)row * 256 + c4);
        *(uint2*)(Vs + row * AST + c4) = *(const uint2*)(V + base + (size_t)row * 256 + c4);
    }
    __syncthreads();

    const int ch0 = (w >> 1) * 32;
    const int rbase = (w & 1) * 32;

    const __half* Qr[2][2];
#pragma unroll
    for (int mi = 0; mi < 2; mi++) {
        int r = rbase + mi * 16 + g;
        Qr[mi][0] = Q + base + (size_t)r * 256 + ch0;
        Qr[mi][1] = Q + base + (size_t)(r + 8) * 256 + ch0;
    }

    const uint32_t KhA = smem_u32(Kh), VsA = smem_u32(Vs);

    float acc[2][8][4];
#pragma unroll
    for (int mi = 0; mi < 2; mi++)
#pragma unroll
        for (int ni = 0; ni < 8; ni++)
#pragma unroll
            for (int r = 0; r < 4; r++) acc[mi][ni][r] = 0.f;

#pragma unroll
    for (int ks = 0; ks < 2; ks++) {
        uint32_t a[2][4], bb[8][2];
#pragma unroll
        for (int mi = 0; mi < 2; mi++) {
            a[mi][0] = *(const uint32_t*)(Qr[mi][0] + ks * 16 + 2 * tg);
            a[mi][1] = *(const uint32_t*)(Qr[mi][1] + ks * 16 + 2 * tg);
            a[mi][2] = *(const uint32_t*)(Qr[mi][0] + ks * 16 + 8 + 2 * tg);
            a[mi][3] = *(const uint32_t*)(Qr[mi][1] + ks * 16 + 8 + 2 * tg);
        }
#pragma unroll
        for (int p = 0; p < 4; p++) {
            uint32_t r4[4];
            ldsm4(r4, KhA + (uint32_t)((p * 16 + ((bg2 >> 1) << 3) + bj) * AST
                                       + ch0 + ks * 16 + ((bg2 & 1) << 3)) * 2);
            bb[2 * p][0] = r4[0]; bb[2 * p][1] = r4[1];
            bb[2 * p + 1][0] = r4[2]; bb[2 * p + 1][1] = r4[3];
        }
#pragma unroll
        for (int mi = 0; mi < 2; mi++)
#pragma unroll
            for (int ni = 0; ni < 8; ni++)
                mma_f16(acc[mi][ni], a[mi], bb[ni]);
    }

    const float* mp = mask + (size_t)(b & (NW - 1)) * NTOK * NTOK;
#pragma unroll
    for (int mi = 0; mi < 2; mi++) {
#pragma unroll
        for (int rh = 0; rh < 2; rh++) {
            const int row = rbase + mi * 16 + rh * 8 + g;
            const int o = rh * 2;
            float mx = -1e30f;
#pragma unroll
            for (int ni = 0; ni < 8; ni++) {
                float2 mv = *(const float2*)(mp + row * 64 + ni * 8 + 2 * tg);
                acc[mi][ni][o]     = fmaf(acc[mi][ni][o], scale, mv.x);
                acc[mi][ni][o + 1] = fmaf(acc[mi][ni][o + 1], scale, mv.y);
                mx = fmaxf(mx, fmaxf(acc[mi][ni][o], acc[mi][ni][o + 1]));
            }
            mx = fmaxf(mx, __shfl_xor_sync(0xffffffffu, mx, 1));
            mx = fmaxf(mx, __shfl_xor_sync(0xffffffffu, mx, 2));
            float sum = 0.f;
#pragma unroll
            for (int ni = 0; ni < 8; ni++) {
                acc[mi][ni][o]     = __expf(acc[mi][ni][o] - mx);
                acc[mi][ni][o + 1] = __expf(acc[mi][ni][o + 1] - mx);
                sum += acc[mi][ni][o] + acc[mi][ni][o + 1];
            }
            sum += __shfl_xor_sync(0xffffffffu, sum, 1);
            sum += __shfl_xor_sync(0xffffffffu, sum, 2);
            const float inv = 1.f / sum;
#pragma unroll
            for (int ni = 0; ni < 8; ni++) {
                acc[mi][ni][o]     *= inv;
                acc[mi][ni][o + 1] *= inv;
            }
        }
    }

    __half* Pw = Pp + w * 32 * AST;
#pragma unroll
    for (int mi = 0; mi < 2; mi++)
#pragma unroll
        for (int rh = 0; rh < 2; rh++) {
            const int rl = mi * 16 + rh * 8 + g;
#pragma unroll
            for (int ni = 0; ni < 8; ni++)
                *(__half2*)(Pw + rl * AST + ni * 8 + 2 * tg) =
                    __floats2half2_rn(acc[mi][ni][rh * 2], acc[mi][ni][rh * 2 + 1]);
        }
    __syncwarp();

    const uint32_t PwA = smem_u32(Pw);
    float acc2[2][4][4];
#pragma unroll
    for (int mi = 0; mi < 2; mi++)
#pragma unroll
        for (int ni = 0; ni < 4; ni++)
#pragma unroll
            for (int r = 0; r < 4; r++) acc2[mi][ni][r] = 0.f;

#pragma unroll
    for (int ks = 0; ks < 4; ks++) {
        uint32_t a[2][4], bb[4][2];
#pragma unroll
        for (int mi = 0; mi < 2; mi++)
            ldsm4(a[mi], PwA + (uint32_t)((mi * 16 + lmrow) * AST + ks * 16 + lmk) * 2);
#pragma unroll
        for (int p = 0; p < 2; p++) {
            uint32_t r4[4];
            int tok = ks * 16 + ((bg2 & 1) << 3) + bj;
            int chc = ch0 + p * 16 + ((bg2 >> 1) << 3);
            ldsm4t(r4, VsA + (uint32_t)(tok * AST + chc) * 2);
            bb[2 * p][0] = r4[0]; bb[2 * p][1] = r4[1];
            bb[2 * p + 1][0] = r4[2]; bb[2 * p + 1][1] = r4[3];
        }
#pragma unroll
        for (int mi = 0; mi < 2; mi++)
#pragma unroll
            for (int ni = 0; ni < 4; ni++)
                mma_f16(acc2[mi][ni], a[mi], bb[ni]);
    }

    // ---- LePE: halo + weights ready; add conv to O, write S ----
    CP_WAIT0();
    __syncthreads();

#pragma unroll
    for (int mi = 0; mi < 2; mi++) {
#pragma unroll
        for (int rh = 0; rh < 2; rh++) {
            const int row = rbase + mi * 16 + rh * 8 + g;
            const int py = row >> 3, px = row & 7;
#pragma unroll
            for (int ni = 0; ni < 4; ni++) {
#pragma unroll
                for (int c2 = 0; c2 < 2; c2++) {
                    const int c = ch0 + ni * 8 + 2 * tg + c2;
                    const float* wc9 = Wsm + c * 9;
                    float v = Bsm[c];
#pragma unroll
                    for (int dy = 0; dy < 3; dy++)
#pragma unroll
                        for (int dx = 0; dx < 3; dx++)
                            v = fmaf(__half2float(Halo[((py + dy) * 10 + px + dx) * HSTR + c]),
                                     wc9[dy * 3 + dx], v);
                    acc2[mi][ni][rh * 2 + c2] += v;
                }
            }
        }
    }

#pragma unroll
    for (int mi = 0; mi < 2; mi++) {
        const int row = rbase + mi * 16 + g;
#pragma unroll
        for (int ni = 0; ni < 4; ni++) {
            const int col = hp * 64 + ch0 + ni * 8 + 2 * tg;
            *(__half2*)(S + (size_t)(b * NTOK + row) * 256 + col) =
                __floats2half2_rn(acc2[mi][ni][0], acc2[mi][ni][1]);
            *(__half2*)(S + (size_t)(b * NTOK + row + 8) * 256 + col) =
                __floats2half2_rn(acc2[mi][ni][2], acc2[mi][ni][3]);
        }
    }
}

// ---------------------------------------------------------------------------
// kernel_launch  (gemm Q is launch #5 -> ncu profiles it)
// ---------------------------------------------------------------------------
extern "C" void kernel_launch(void* const* d_in, const int* in_sizes, int n_in,
                              void* d_out, int out_size)
{
    const float* x    = (const float*)d_in[0];
    const float* y    = (const float*)d_in[1];
    const float* mask = (const float*)d_in[2];
    const float* Wq   = (const float*)d_in[3];
    const float* bq   = (const float*)d_in[4];
    const float* Wk   = (const float*)d_in[5];
    const float* bk   = (const float*)d_in[6];
    const float* Wv   = (const float*)d_in[7];
    const float* bv   = (const float*)d_in[8];
    const float* rw   = (const float*)d_in[9];
    const float* rb   = (const float*)d_in[10];
    const float* Wp   = (const float*)d_in[11];
    const float* bp   = (const float*)d_in[12];
    float* out        = (float*)d_out;

    __half *pxh, *pyh, *pWq, *pWk, *pWv, *pWp, *pQ, *pK, *pV, *pS;
    cudaGetSymbolAddress((void**)&pxh, g_xh);
    cudaGetSymbolAddress((void**)&pyh, g_yh);
    cudaGetSymbolAddress((void**)&pWq, g_Wqh);
    cudaGetSymbolAddress((void**)&pWk, g_Wkh);
    cudaGetSymbolAddress((void**)&pWv, g_Wvh);
    cudaGetSymbolAddress((void**)&pWp, g_Wph);
    cudaGetSymbolAddress((void**)&pQ, g_Q);
    cudaGetSymbolAddress((void**)&pK, g_K);
    cudaGetSymbolAddress((void**)&pV, g_V);
    cudaGetSymbolAddress((void**)&pS, g_S);

    static bool attr_done = false;
    if (!attr_done) {
        cudaFuncSetAttribute(gemm_f16k<__half>, cudaFuncAttributeMaxDynamicSharedMemorySize, GEMM_SMEM);
        cudaFuncSetAttribute(gemm_f16k<float>,  cudaFuncAttributeMaxDynamicSharedMemorySize, GEMM_SMEM);
        cudaFuncSetAttribute(attn_lepe, cudaFuncAttributeMaxDynamicSharedMemorySize, ATTN_SMEM);
        attr_done = true;
    }

    const int NBIG = (int)((size_t)MTOT * CH / (256 * 8));   // 32768 blocks
    const int NW2 = CH * CH / (256 * 8);                      // 32 blocks
    cvt_f16<<<NBIG, 256>>>(x, pxh);     // launch 0
    cvt_f16<<<NBIG, 256>>>(y, pyh);     // launch 1
    cvt_f16<<<NW2, 256>>>(Wq, pWq);     // launch 2
    cvt_f16<<<NW2, 256>>>(Wk, pWk);     // launch 3
    cvt_f16<<<NW2, 256>>>(Wv, pWv);     // launch 4

    dim3 gg(2, MTOT / 128);
    gemm_f16k<__half><<<gg, 256, GEMM_SMEM>>>(pxh, pWq, bq, pQ);   // launch 5 (profiled)
    gemm_f16k<__half><<<gg, 256, GEMM_SMEM>>>(pyh, pWk, bk, pK);
    gemm_f16k<__half><<<gg, 256, GEMM_SMEM>>>(pxh, pWv, bv, pV);

    attn_lepe<<<dim3(4, BWIN), 128, ATTN_SMEM>>>(pQ, pK, pV, mask, rw, rb, pS);

    cvt_f16<<<NW2, 256>>>(Wp, pWp);
    gemm_f16k<float><<<gg, 256, GEMM_SMEM>>>(pS, pWp, bp, out);
}

// round 12
// speedup vs baseline: 1.6261x; 1.0003x over previous
#include <cuda_runtime.h>
#include <cuda_fp16.h>
#include <cstdint>

// Problem constants (fixed by setup_inputs)
#define BATCH 4
#define IMG 256
#define WS 8
#define NW 1024              // (256/8)^2
#define BWIN (BATCH * NW)    // 4096 windows
#define NTOK 64              // WS*WS
#define CH 256
#define HEADS 8
#define HD 32
#define MTOT (BWIN * NTOK)   // 262144 rows

// Scratch
__device__ __half g_Wqh[CH * CH];
__device__ __half g_Wkh[CH * CH];
__device__ __half g_Wvh[CH * CH];
__device__ __half g_Wph[CH * CH];
__device__ __half g_Q[(size_t)MTOT * CH];
__device__ __half g_K[(size_t)MTOT * CH];
__device__ __half g_V[(size_t)MTOT * CH];
__device__ __half g_S[(size_t)MTOT * CH];

// ---------------------------------------------------------------------------
// helpers
// ---------------------------------------------------------------------------
__device__ __forceinline__ uint32_t smem_u32(const void* p) {
    uint32_t a;
    asm("{ .reg .u64 t; cvta.to.shared.u64 t, %1; cvt.u32.u64 %0, t; }" : "=r"(a) : "l"(p));
    return a;
}
__device__ __forceinline__ void mma_f16(float* d, const uint32_t* a, const uint32_t* b) {
    asm volatile(
        "mma.sync.aligned.m16n8k16.row.col.f32.f16.f16.f32 "
        "{%0,%1,%2,%3}, {%4,%5,%6,%7}, {%8,%9}, {%0,%1,%2,%3};"
        : "+f"(d[0]), "+f"(d[1]), "+f"(d[2]), "+f"(d[3])
        : "r"(a[0]), "r"(a[1]), "r"(a[2]), "r"(a[3]), "r"(b[0]), "r"(b[1]));
}
__device__ __forceinline__ void ldsm4(uint32_t* r, uint32_t addr) {
    asm volatile("ldmatrix.sync.aligned.m8n8.x4.shared.b16 {%0,%1,%2,%3}, [%4];"
        : "=r"(r[0]), "=r"(r[1]), "=r"(r[2]), "=r"(r[3]) : "r"(addr));
}
__device__ __forceinline__ void ldsm4t(uint32_t* r, uint32_t addr) {
    asm volatile("ldmatrix.sync.aligned.m8n8.x4.trans.shared.b16 {%0,%1,%2,%3}, [%4];"
        : "=r"(r[0]), "=r"(r[1]), "=r"(r[2]), "=r"(r[3]) : "r"(addr));
}
__device__ __forceinline__ uint32_t h2u(__half2 h) { return *reinterpret_cast<uint32_t*>(&h); }
__device__ __forceinline__ void cp16(void* dst, const void* src) {
    uint32_t d = smem_u32(dst);
    asm volatile("cp.async.cg.shared.global [%0], [%1], 16;" :: "r"(d), "l"(src));
}
__device__ __forceinline__ void cp8(void* dst, const void* src) {
    uint32_t d = smem_u32(dst);
    asm volatile("cp.async.ca.shared.global [%0], [%1], 8;" :: "r"(d), "l"(src));
}
#define CP_COMMIT() asm volatile("cp.async.commit_group;" ::: "memory")
#define CP_WAIT0()  asm volatile("cp.async.wait_group 0;" ::: "memory")
#define CP_WAIT1()  asm volatile("cp.async.wait_group 1;" ::: "memory")

// ---------------------------------------------------------------------------
// fp32 -> f16 convert (weights only; 8 elem/thread)
// ---------------------------------------------------------------------------
__global__ __launch_bounds__(256) void cvt_f16(
    const float* __restrict__ in, __half* __restrict__ out)
{
    size_t i = ((size_t)blockIdx.x * 256 + threadIdx.x) * 8;
    float4 a = *(const float4*)(in + i);
    float4 b = *(const float4*)(in + i + 4);
    uint4 o;
    o.x = h2u(__floats2half2_rn(a.x, a.y));
    o.y = h2u(__floats2half2_rn(a.z, a.w));
    o.z = h2u(__floats2half2_rn(b.x, b.y));
    o.w = h2u(__floats2half2_rn(b.z, b.w));
    *(uint4*)(out + i) = o;
}

// ---------------------------------------------------------------------------
// GEMM with fp32 A (register-pipelined, in-kernel f16 convert):
// C[M x 256] = A[M x 256] @ Wsel^T + bias, Wsel per blockIdx.x>>1.
// Block 256 thr (8 warps 2x4), tile 128x128, K chunks of 32 (8 chunks).
// smem: A/B f16 tiles stride 40 halves, double-buffered = 40 KB.
// ---------------------------------------------------------------------------
#define QSTR 40
#define QGEMM_SMEM (2 * 2 * 128 * QSTR * 2)   // 40960 B

__global__ __launch_bounds__(256) void gemm_qv(
    const float* __restrict__ A,
    const __half* __restrict__ W0, const __half* __restrict__ W1,
    const float* __restrict__ b0, const float* __restrict__ b1,
    __half* __restrict__ C0, __half* __restrict__ C1)
{
    extern __shared__ __half qsm[];
    __half* Ah = qsm;                    // [2][128*QSTR]
    __half* Bh = qsm + 2 * 128 * QSTR;   // [2][128*QSTR]

    const int wsel = blockIdx.x >> 1;
    const int n0 = (blockIdx.x & 1) * 128;
    const __half* Wt = wsel ? W1 : W0;
    const float* bias = wsel ? b1 : b0;
    __half* C = wsel ? C1 : C0;

    const int t = threadIdx.x, lane = t & 31, warp = t >> 5;
    const int wm = warp & 1, wn = warp >> 1;
    const int m0 = blockIdx.y * 128;
    const int g = lane >> 2, tg = lane & 3;

    const uint32_t aBase = smem_u32(Ah), bBase = smem_u32(Bh);
    const int lmrow = lane & 15, lmk = (lane >> 4) << 3;
    const int bg2 = lane >> 3, bj = lane & 7;

    // A register pipeline: thread t covers row t>>1, cols (t&1)*16 .. +15
    const int arow = t >> 1, acol = (t & 1) * 16;
    const float* Aptr = A + (size_t)(m0 + arow) * 256 + acol;

    float acc[4][4][4];
#pragma unroll
    for (int mi = 0; mi < 4; mi++)
#pragma unroll
        for (int ni = 0; ni < 4; ni++)
#pragma unroll
            for (int r = 0; r < 4; r++) acc[mi][ni][r] = 0.f;

    // prologue: chunk 0 -> regs; B chunk 0 -> smem
    float4 ar[4];
#pragma unroll
    for (int j = 0; j < 4; j++) ar[j] = *(const float4*)(Aptr + j * 4);
    {
        const int brow = t >> 1, bseg = (t & 1) * 2;  // 2 cp16 per thread
#pragma unroll
        for (int i = 0; i < 2; i++)
            cp16(Bh + brow * QSTR + (bseg + i) * 8,
                 Wt + (size_t)(n0 + brow) * 256 + (bseg + i) * 8);
    }
    CP_COMMIT();

    for (int kc = 0; kc < 8; kc++) {
        // store A regs (chunk kc) to Abuf[kc&1] as f16
        __half* Ad = Ah + (kc & 1) * 128 * QSTR + arow * QSTR + acol;
#pragma unroll
        for (int j = 0; j < 4; j++) {
            uint2 pv;
            pv.x = h2u(__floats2half2_rn(ar[j].x, ar[j].y));
            pv.y = h2u(__floats2half2_rn(ar[j].z, ar[j].w));
            *(uint2*)(Ad + j * 4) = pv;
        }
        // issue A loads for chunk kc+1
        if (kc < 7) {
#pragma unroll
            for (int j = 0; j < 4; j++)
                ar[j] = *(const float4*)(Aptr + (kc + 1) * 32 + j * 4);
        }
        // B chunk kc+1
        if (kc < 7) {
            const int brow = t >> 1, bseg = (t & 1) * 2;
            __half* Bd = Bh + ((kc + 1) & 1) * 128 * QSTR;
#pragma unroll
            for (int i = 0; i < 2; i++)
                cp16(Bd + brow * QSTR + (bseg + i) * 8,
                     Wt + (size_t)(n0 + brow) * 256 + (kc + 1) * 32 + (bseg + i) * 8);
            CP_COMMIT();
            CP_WAIT1();
        } else {
            CP_WAIT0();
        }
        __syncthreads();

        const uint32_t aB = aBase + (uint32_t)((kc & 1) * 128 * QSTR) * 2;
        const uint32_t bB = bBase + (uint32_t)((kc & 1) * 128 * QSTR) * 2;
#pragma unroll
        for (int ks = 0; ks < 2; ks++) {
            const int k0h = ks * 16;
            uint32_t a[4][4], b[4][2];
#pragma unroll
            for (int mi = 0; mi < 4; mi++)
                ldsm4(a[mi], aB + (uint32_t)((wm * 64 + mi * 16 + lmrow) * QSTR + k0h + lmk) * 2);
#pragma unroll
            for (int p = 0; p < 2; p++) {
                uint32_t r4[4];
                ldsm4(r4, bB + (uint32_t)((wn * 32 + p * 16 + ((bg2 >> 1) << 3) + bj) * QSTR
                                          + k0h + ((bg2 & 1) << 3)) * 2);
                b[2 * p][0] = r4[0]; b[2 * p][1] = r4[1];
                b[2 * p + 1][0] = r4[2]; b[2 * p + 1][1] = r4[3];
            }
#pragma unroll
            for (int mi = 0; mi < 4; mi++)
#pragma unroll
                for (int ni = 0; ni < 4; ni++)
                    mma_f16(acc[mi][ni], a[mi], b[ni]);
        }
    }

    float bv[4][2];
#pragma unroll
    for (int ni = 0; ni < 4; ni++) {
        int col = n0 + wn * 32 + ni * 8 + 2 * tg;
        bv[ni][0] = __ldg(bias + col);
        bv[ni][1] = __ldg(bias + col + 1);
    }
#pragma unroll
    for (int mi = 0; mi < 4; mi++) {
        int r0 = m0 + wm * 64 + mi * 16 + g;
#pragma unroll
        for (int ni = 0; ni < 4; ni++) {
            int col = n0 + wn * 32 + ni * 8 + 2 * tg;
            *(__half2*)(C + (size_t)r0 * 256 + col) =
                __floats2half2_rn(acc[mi][ni][0] + bv[ni][0], acc[mi][ni][1] + bv[ni][1]);
            *(__half2*)(C + (size_t)(r0 + 8) * 256 + col) =
                __floats2half2_rn(acc[mi][ni][2] + bv[ni][0], acc[mi][ni][3] + bv[ni][1]);
        }
    }
}

// ---------------------------------------------------------------------------
// GEMM pure f16 (final projection; round-10 structure)
// ---------------------------------------------------------------------------
#define KC 64
#define GSTR 72
#define GEMM_SMEM (2 * 2 * 128 * GSTR * 2)   // 73728 B

__device__ __forceinline__ void load_chunk_async(
    const __half* Ap, const __half* Bp, __half* Ad, __half* Bd, int t)
{
    const int c16 = (t & 7) * 8;
    const int row0 = t >> 3;
#pragma unroll
    for (int i = 0; i < 4; i++) {
        int row = row0 + i * 32;
        cp16(Ad + row * GSTR + c16, Ap + (size_t)row * 256 + c16);
        cp16(Bd + row * GSTR + c16, Bp + (size_t)row * 256 + c16);
    }
}

__global__ __launch_bounds__(256) void gemm_f16f(
    const __half* __restrict__ A, const __half* __restrict__ Wt,
    const float* __restrict__ bias, float* __restrict__ C)
{
    extern __shared__ __half hsm[];
    __half* Ah = hsm;
    __half* Bh = hsm + 2 * 128 * GSTR;

    const int t = threadIdx.x, lane = t & 31, warp = t >> 5;
    const int wm = warp & 1, wn = warp >> 1;
    const int m0 = blockIdx.y * 128, n0 = blockIdx.x * 128;
    const int g = lane >> 2, tg = lane & 3;

    const uint32_t aBase = smem_u32(Ah), bBase = smem_u32(Bh);
    const int lmrow = lane & 15, lmk = (lane >> 4) << 3;
    const int bg2 = lane >> 3, bj = lane & 7;

    float acc[4][4][4];
#pragma unroll
    for (int mi = 0; mi < 4; mi++)
#pragma unroll
        for (int ni = 0; ni < 4; ni++)
#pragma unroll
            for (int r = 0; r < 4; r++) acc[mi][ni][r] = 0.f;

    load_chunk_async(A + (size_t)m0 * 256, Wt + (size_t)n0 * 256, Ah, Bh, t);
    CP_COMMIT();

    for (int kc = 0; kc < 4; kc++) {
        CP_WAIT0();
        __syncthreads();
        if (kc < 3) {
            int buf = (kc + 1) & 1;
            load_chunk_async(A + (size_t)m0 * 256 + (kc + 1) * KC,
                             Wt + (size_t)n0 * 256 + (kc + 1) * KC,
                             Ah + buf * 128 * GSTR, Bh + buf * 128 * GSTR, t);
            CP_COMMIT();
        }
        const uint32_t aB = aBase + (uint32_t)((kc & 1) * 128 * GSTR) * 2;
        const uint32_t bB = bBase + (uint32_t)((kc & 1) * 128 * GSTR) * 2;
#pragma unroll
        for (int ks = 0; ks < 4; ks++) {
            const int k0h = ks * 16;
            uint32_t a[4][4], b[4][2];
#pragma unroll
            for (int mi = 0; mi < 4; mi++)
                ldsm4(a[mi], aB + (uint32_t)((wm * 64 + mi * 16 + lmrow) * GSTR + k0h + lmk) * 2);
#pragma unroll
            for (int p = 0; p < 2; p++) {
                uint32_t r4[4];
                ldsm4(r4, bB + (uint32_t)((wn * 32 + p * 16 + ((bg2 >> 1) << 3) + bj) * GSTR
                                          + k0h + ((bg2 & 1) << 3)) * 2);
                b[2 * p][0] = r4[0]; b[2 * p][1] = r4[1];
                b[2 * p + 1][0] = r4[2]; b[2 * p + 1][1] = r4[3];
            }
#pragma unroll
            for (int mi = 0; mi < 4; mi++)
#pragma unroll
                for (int ni = 0; ni < 4; ni++)
                    mma_f16(acc[mi][ni], a[mi], b[ni]);
        }
        __syncthreads();
    }

    float bv[4][2];
#pragma unroll
    for (int ni = 0; ni < 4; ni++) {
        int col = n0 + wn * 32 + ni * 8 + 2 * tg;
        bv[ni][0] = __ldg(bias + col);
        bv[ni][1] = __ldg(bias + col + 1);
    }
#pragma unroll
    for (int mi = 0; mi < 4; mi++) {
        int r0 = m0 + wm * 64 + mi * 16 + g;
#pragma unroll
        for (int ni = 0; ni < 4; ni++) {
            int col = n0 + wn * 32 + ni * 8 + 2 * tg;
            *(float2*)(C + (size_t)r0 * 256 + col) =
                make_float2(acc[mi][ni][0] + bv[ni][0], acc[mi][ni][1] + bv[ni][1]);
            *(float2*)(C + (size_t)(r0 + 8) * 256 + col) =
                make_float2(acc[mi][ni][2] + bv[ni][0], acc[mi][ni][3] + bv[ni][1]);
        }
    }
}

// ---------------------------------------------------------------------------
// Attention f16 + fused LePE (round-11 structure, unchanged)
// ---------------------------------------------------------------------------
#define AST 72
#define HSTR 68
#define ATTN_SMEM 53024

__global__ __launch_bounds__(128, 4) void attn_lepe(
    const __half* __restrict__ Q, const __half* __restrict__ K,
    const __half* __restrict__ V, const float* __restrict__ mask,
    const float* __restrict__ rw, const float* __restrict__ rb,
    __half* __restrict__ S)
{
    extern __shared__ __half asmh[];
    __half* Kh   = asmh;
    __half* Vs   = asmh + 4608;
    __half* Pp   = asmh + 9216;
    __half* Halo = asmh + 18432;
    float*  Wsm  = (float*)(asmh + 25232);
    float*  Bsm  = Wsm + 576;

    const int hp = blockIdx.x;
    const int b  = blockIdx.y;
    const int t = threadIdx.x, lane = t & 31, w = t >> 5;
    const int g = lane >> 2, tg = lane & 3;
    const int bg2 = lane >> 3, bj = lane & 7;
    const int lmrow = lane & 15, lmk = (lane >> 4) << 3;
    const size_t base = (size_t)b * NTOK * CH + hp * 64;
    const float scale = 0.17677669529663687f;

    const int bi = b >> 10, win = b & 1023;
    const int hh0 = (win >> 5) * 8, ww0 = (win & 31) * 8;
#pragma unroll
    for (int i = t; i < 160; i += 128) {
        if (i < 144) cp16(Wsm + i * 4, rw + (size_t)hp * 576 + i * 4);
        else         cp16(Bsm + (i - 144) * 4, rb + hp * 64 + (i - 144) * 4);
    }
#pragma unroll
    for (int i = 0; i < 13; i++) {
        int linear = t + i * 128;
        if (linear < 1600) {
            int p = linear >> 4, c4 = (linear & 15) * 4;
            int py = p / 10, px = p % 10;
            int hh = hh0 + py - 1, ww = ww0 + px - 1;
            __half* dst = Halo + p * HSTR + c4;
            if (hh >= 0 && hh < IMG && ww >= 0 && ww < IMG) {
                size_t src = ((size_t)(bi * NW + (hh >> 3) * 32 + (ww >> 3)) * NTOK
                              + ((hh & 7) * 8 + (ww & 7))) * CH + hp * 64 + c4;
                cp8(dst, Q + src);
            } else {
                *(uint2*)dst = make_uint2(0u, 0u);
            }
        }
    }
    CP_COMMIT();

#pragma unroll
    for (int i = 0; i < 8; i++) {
        int linear = i * 128 + t;
        int row = linear >> 4;
        int c4 = (linear & 15) * 4;
        *(uint2*)(Kh + row * AST + c4) = *(const uint2*)(K + base + (size_t)row * 256 + c4);
        *(uint2*)(Vs + row * AST + c4) = *(const uint2*)(V + base + (size_t)row * 256 + c4);
    }
    __syncthreads();

    const int ch0 = (w >> 1) * 32;
    const int rbase = (w & 1) * 32;

    const __half* Qr[2][2];
#pragma unroll
    for (int mi = 0; mi < 2; mi++) {
        int r = rbase + mi * 16 + g;
        Qr[mi][0] = Q + base + (size_t)r * 256 + ch0;
        Qr[mi][1] = Q + base + (size_t)(r + 8) * 256 + ch0;
    }

    const uint32_t KhA = smem_u32(Kh), VsA = smem_u32(Vs);

    float acc[2][8][4];
#pragma unroll
    for (int mi = 0; mi < 2; mi++)
#pragma unroll
        for (int ni = 0; ni < 8; ni++)
#pragma unroll
            for (int r = 0; r < 4; r++) acc[mi][ni][r] = 0.f;

#pragma unroll
    for (int ks = 0; ks < 2; ks++) {
        uint32_t a[2][4], bb[8][2];
#pragma unroll
        for (int mi = 0; mi < 2; mi++) {
            a[mi][0] = *(const uint32_t*)(Qr[mi][0] + ks * 16 + 2 * tg);
            a[mi][1] = *(const uint32_t*)(Qr[mi][1] + ks * 16 + 2 * tg);
            a[mi][2] = *(const uint32_t*)(Qr[mi][0] + ks * 16 + 8 + 2 * tg);
            a[mi][3] = *(const uint32_t*)(Qr[mi][1] + ks * 16 + 8 + 2 * tg);
        }
#pragma unroll
        for (int p = 0; p < 4; p++) {
            uint32_t r4[4];
            ldsm4(r4, KhA + (uint32_t)((p * 16 + ((bg2 >> 1) << 3) + bj) * AST
                                       + ch0 + ks * 16 + ((bg2 & 1) << 3)) * 2);
            bb[2 * p][0] = r4[0]; bb[2 * p][1] = r4[1];
            bb[2 * p + 1][0] = r4[2]; bb[2 * p + 1][1] = r4[3];
        }
#pragma unroll
        for (int mi = 0; mi < 2; mi++)
#pragma unroll
            for (int ni = 0; ni < 8; ni++)
                mma_f16(acc[mi][ni], a[mi], bb[ni]);
    }

    const float* mp = mask + (size_t)(b & (NW - 1)) * NTOK * NTOK;
#pragma unroll
    for (int mi = 0; mi < 2; mi++) {
#pragma unroll
        for (int rh = 0; rh < 2; rh++) {
            const int row = rbase + mi * 16 + rh * 8 + g;
            const int o = rh * 2;
            float mx = -1e30f;
#pragma unroll
            for (int ni = 0; ni < 8; ni++) {
                float2 mv = *(const float2*)(mp + row * 64 + ni * 8 + 2 * tg);
                acc[mi][ni][o]     = fmaf(acc[mi][ni][o], scale, mv.x);
                acc[mi][ni][o + 1] = fmaf(acc[mi][ni][o + 1], scale, mv.y);
                mx = fmaxf(mx, fmaxf(acc[mi][ni][o], acc[mi][ni][o + 1]));
            }
            mx = fmaxf(mx, __shfl_xor_sync(0xffffffffu, mx, 1));
            mx = fmaxf(mx, __shfl_xor_sync(0xffffffffu, mx, 2));
            float sum = 0.f;
#pragma unroll
            for (int ni = 0; ni < 8; ni++) {
                acc[mi][ni][o]     = __expf(acc[mi][ni][o] - mx);
                acc[mi][ni][o + 1] = __expf(acc[mi][ni][o + 1] - mx);
                sum += acc[mi][ni][o] + acc[mi][ni][o + 1];
            }
            sum += __shfl_xor_sync(0xffffffffu, sum, 1);
            sum += __shfl_xor_sync(0xffffffffu, sum, 2);
            const float inv = 1.f / sum;
#pragma unroll
            for (int ni = 0; ni < 8; ni++) {
                acc[mi][ni][o]     *= inv;
                acc[mi][ni][o + 1] *= inv;
            }
        }
    }

    __half* Pw = Pp + w * 32 * AST;
#pragma unroll
    for (int mi = 0; mi < 2; mi++)
#pragma unroll
        for (int rh = 0; rh < 2; rh++) {
            const int rl = mi * 16 + rh * 8 + g;
#pragma unroll
            for (int ni = 0; ni < 8; ni++)
                *(__half2*)(Pw + rl * AST + ni * 8 + 2 * tg) =
                    __floats2half2_rn(acc[mi][ni][rh * 2], acc[mi][ni][rh * 2 + 1]);
        }
    __syncwarp();

    const uint32_t PwA = smem_u32(Pw);
    float acc2[2][4][4];
#pragma unroll
    for (int mi = 0; mi < 2; mi++)
#pragma unroll
        for (int ni = 0; ni < 4; ni++)
#pragma unroll
            for (int r = 0; r < 4; r++) acc2[mi][ni][r] = 0.f;

#pragma unroll
    for (int ks = 0; ks < 4; ks++) {
        uint32_t a[2][4], bb[4][2];
#pragma unroll
        for (int mi = 0; mi < 2; mi++)
            ldsm4(a[mi], PwA + (uint32_t)((mi * 16 + lmrow) * AST + ks * 16 + lmk) * 2);
#pragma unroll
        for (int p = 0; p < 2; p++) {
            uint32_t r4[4];
            int tok = ks * 16 + ((bg2 & 1) << 3) + bj;
            int chc = ch0 + p * 16 + ((bg2 >> 1) << 3);
            ldsm4t(r4, VsA + (uint32_t)(tok * AST + chc) * 2);
            bb[2 * p][0] = r4[0]; bb[2 * p][1] = r4[1];
            bb[2 * p + 1][0] = r4[2]; bb[2 * p + 1][1] = r4[3];
        }
#pragma unroll
        for (int mi = 0; mi < 2; mi++)
#pragma unroll
            for (int ni = 0; ni < 4; ni++)
                mma_f16(acc2[mi][ni], a[mi], bb[ni]);
    }

    CP_WAIT0();
    __syncthreads();

#pragma unroll
    for (int mi = 0; mi < 2; mi++) {
#pragma unroll
        for (int rh = 0; rh < 2; rh++) {
            const int row = rbase + mi * 16 + rh * 8 + g;
            const int py = row >> 3, px = row & 7;
#pragma unroll
            for (int ni = 0; ni < 4; ni++) {
#pragma unroll
                for (int c2 = 0; c2 < 2; c2++) {
                    const int c = ch0 + ni * 8 + 2 * tg + c2;
                    const float* wc9 = Wsm + c * 9;
                    float v = Bsm[c];
#pragma unroll
                    for (int dy = 0; dy < 3; dy++)
#pragma unroll
                        for (int dx = 0; dx < 3; dx++)
                            v = fmaf(__half2float(Halo[((py + dy) * 10 + px + dx) * HSTR + c]),
                                     wc9[dy * 3 + dx], v);
                    acc2[mi][ni][rh * 2 + c2] += v;
                }
            }
        }
    }

#pragma unroll
    for (int mi = 0; mi < 2; mi++) {
        const int row = rbase + mi * 16 + g;
#pragma unroll
        for (int ni = 0; ni < 4; ni++) {
            const int col = hp * 64 + ch0 + ni * 8 + 2 * tg;
            *(__half2*)(S + (size_t)(b * NTOK + row) * 256 + col) =
                __floats2half2_rn(acc2[mi][ni][0], acc2[mi][ni][1]);
            *(__half2*)(S + (size_t)(b * NTOK + row + 8) * 256 + col) =
                __floats2half2_rn(acc2[mi][ni][2], acc2[mi][ni][3]);
        }
    }
}

// ---------------------------------------------------------------------------
// kernel_launch
// ---------------------------------------------------------------------------
extern "C" void kernel_launch(void* const* d_in, const int* in_sizes, int n_in,
                              void* d_out, int out_size)
{
    const float* x    = (const float*)d_in[0];
    const float* y    = (const float*)d_in[1];
    const float* mask = (const float*)d_in[2];
    const float* Wq   = (const float*)d_in[3];
    const float* bq   = (const float*)d_in[4];
    const float* Wk   = (const float*)d_in[5];
    const float* bk   = (const float*)d_in[6];
    const float* Wv   = (const float*)d_in[7];
    const float* bv   = (const float*)d_in[8];
    const float* rw   = (const float*)d_in[9];
    const float* rb   = (const float*)d_in[10];
    const float* Wp   = (const float*)d_in[11];
    const float* bp   = (const float*)d_in[12];
    float* out        = (float*)d_out;

    __half *pWq, *pWk, *pWv, *pWp, *pQ, *pK, *pV, *pS;
    cudaGetSymbolAddress((void**)&pWq, g_Wqh);
    cudaGetSymbolAddress((void**)&pWk, g_Wkh);
    cudaGetSymbolAddress((void**)&pWv, g_Wvh);
    cudaGetSymbolAddress((void**)&pWp, g_Wph);
    cudaGetSymbolAddress((void**)&pQ, g_Q);
    cudaGetSymbolAddress((void**)&pK, g_K);
    cudaGetSymbolAddress((void**)&pV, g_V);
    cudaGetSymbolAddress((void**)&pS, g_S);

    static bool attr_done = false;
    if (!attr_done) {
        cudaFuncSetAttribute(gemm_qv,  cudaFuncAttributeMaxDynamicSharedMemorySize, QGEMM_SMEM);
        cudaFuncSetAttribute(gemm_f16f, cudaFuncAttributeMaxDynamicSharedMemorySize, GEMM_SMEM);
        cudaFuncSetAttribute(attn_lepe, cudaFuncAttributeMaxDynamicSharedMemorySize, ATTN_SMEM);
        attr_done = true;
    }

    const int NW2 = CH * CH / (256 * 8);   // 32 blocks
    cvt_f16<<<NW2, 256>>>(Wq, pWq);
    cvt_f16<<<NW2, 256>>>(Wk, pWk);
    cvt_f16<<<NW2, 256>>>(Wv, pWv);
    cvt_f16<<<NW2, 256>>>(Wp, pWp);

    // Q + V fused (x read once); K separate (y)
    gemm_qv<<<dim3(4, MTOT / 128), 256, QGEMM_SMEM>>>(x, pWq, pWv, bq, bv, pQ, pV);
    gemm_qv<<<dim3(2, MTOT / 128), 256, QGEMM_SMEM>>>(y, pWk, pWk, bk, bk, pK, pK);

    attn_lepe<<<dim3(4, BWIN), 128, ATTN_SMEM>>>(pQ, pK, pV, mask, rw, rb, pS);

    gemm_f16f<<<dim3(2, MTOT / 128), 256, GEMM_SMEM>>>(pS, pWp, bp, out);
}